// round 8
// baseline (speedup 1.0000x reference)
#include <cuda_runtime.h>
#include <cstdint>
#include <math.h>

// Problem constants
#define BSZ  8
#define CDIM 4096
#define TDIM 512
#define NH   8
#define HDIM 64
#define ODIM 512
#define SCALE_INV (1.0f / 22.62741699796952f)   // 1/sqrt(512)

// ---------------- scratch (static device globals; allocation-free) ----------
// g_Pd[b][t][1024]: cols 0-511 = K-half-0 partial of P, 512-1023 = half-1.
// (tf32-pre-rounded)  U = (P0+P1)@Wk^T == [P0|P1] @ [Wk|Wk]^T over K=1024.
__device__ __align__(256) float g_Pd[BSZ * TDIM * 1024];
__device__ __align__(256) float g_U [BSZ * NH * TDIM * HDIM];
__device__ __align__(256) float g_W [BSZ * NH * HDIM * HDIM];  // W^T, tf32-pre-rounded
__device__ __align__(256) float g_Z [BSZ * TDIM * TDIM];       // tf32-pre-rounded
__device__ __align__(256) float g_G [BSZ * TDIM * TDIM];       // tf32-pre-rounded

// ---------------- helpers ----------------
__device__ __forceinline__ unsigned f2tf32(float x) {
    unsigned r;
    asm("cvt.rna.tf32.f32 %0, %1;" : "=r"(r) : "f"(x));
    return r;
}

template<bool PRE>
__device__ __forceinline__ unsigned frag_bits(float x) {
    return PRE ? __float_as_uint(x) : f2tf32(x);
}

__device__ __forceinline__ uint32_t smem_u32(const void* p) {
    uint32_t a;
    asm("{ .reg .u64 t; cvta.to.shared.u64 t, %1; cvt.u32.u64 %0, t; }" : "=r"(a) : "l"(p));
    return a;
}

__device__ __forceinline__ void cp16(uint32_t dst, const float* src) {
    asm volatile("cp.async.cg.shared.global [%0], [%1], 16;" :: "r"(dst), "l"(src));
}
#define CP_COMMIT() asm volatile("cp.async.commit_group;" ::: "memory")
#define CP_WAIT1()  asm volatile("cp.async.wait_group 1;"  ::: "memory")

__device__ __forceinline__ void mma_tf32(float* c, const unsigned* a, const unsigned* b) {
    asm("mma.sync.aligned.m16n8k8.row.col.f32.tf32.tf32.f32 "
        "{%0,%1,%2,%3},{%4,%5,%6,%7},{%8,%9},{%0,%1,%2,%3};"
        : "+f"(c[0]), "+f"(c[1]), "+f"(c[2]), "+f"(c[3])
        : "r"(a[0]), "r"(a[1]), "r"(a[2]), "r"(a[3]),
          "r"(b[0]), "r"(b[1]));
}

// =============================================================================
// NEW engine: 128(M) x 64(N) CTA tile, BK=32, 256 thr (8 warps = 4M x 2N,
// warp tile 32x32), 2-stage cp.async, BOTH fragment operands double-buffered,
// conflict-free pitches (A-scatter 136, B-scatter 72), occupancy 3.
// =============================================================================
template<bool AKC, bool BKC, bool APRE, bool BPRE, bool DPRE>
__device__ __forceinline__ void gemm_db(const float* __restrict__ A, int lda,
                                        const float* __restrict__ B, int ldb,
                                        unsigned kmaskB,
                                        int NC, float* __restrict__ D, int ldd)
{
    extern __shared__ float sm[];
    constexpr int ASTAGE = AKC ? 128 * 36 : 32 * 136;
    constexpr int BSTAGE = BKC ? 64 * 36 : 32 * 72;
    constexpr int STAGE  = ASTAGE + BSTAGE;

    const int tid  = threadIdx.x;
    const int lane = tid & 31;
    const int w    = tid >> 5;
    const int g    = lane >> 2;
    const int qd   = lane & 3;
    const int mb   = (w & 3) * 32;
    const int nb   = (w >> 2) * 32;

    auto issue = [&](int c) {
        float* stA = sm + (c & 1) * STAGE;
        if (AKC) {
#pragma unroll
            for (int it = 0; it < 4; it++) {
                int i   = tid + it * 256;
                int row = i >> 3, kc = (i & 7) * 4;
                cp16(smem_u32(stA + row * 36 + kc),
                     A + (size_t)row * lda + (size_t)c * 32 + kc);
            }
        } else {
#pragma unroll
            for (int it = 0; it < 4; it++) {
                int i  = tid + it * 256;
                int kr = i >> 5, mc = (i & 31) * 4;
                cp16(smem_u32(stA + kr * 136 + mc),
                     A + (size_t)(c * 32 + kr) * lda + mc);
            }
        }
        float* stB = stA + ASTAGE;
        unsigned koff = ((unsigned)c * 32u) & kmaskB;
        if (BKC) {
#pragma unroll
            for (int it = 0; it < 2; it++) {
                int i   = tid + it * 256;
                int row = i >> 3, kc = (i & 7) * 4;
                cp16(smem_u32(stB + row * 36 + kc),
                     B + (size_t)row * ldb + koff + kc);
            }
        } else {
#pragma unroll
            for (int it = 0; it < 2; it++) {
                int i  = tid + it * 256;
                int kr = i >> 4, nc = (i & 15) * 4;
                cp16(smem_u32(stB + kr * 72 + nc),
                     B + (size_t)(koff + kr) * ldb + nc);
            }
        }
    };

    auto loadA = [&](const float* As, int ks, unsigned af[2][4]) {
        const int kk = ks * 8;
#pragma unroll
        for (int mi = 0; mi < 2; mi++) {
            const int m = mb + mi * 16 + g;
            if (AKC) {
                const float* p = As + m * 36 + kk + qd;
                af[mi][0] = frag_bits<APRE>(p[0]);
                af[mi][1] = frag_bits<APRE>(p[8 * 36]);
                af[mi][2] = frag_bits<APRE>(p[4]);
                af[mi][3] = frag_bits<APRE>(p[8 * 36 + 4]);
            } else {
                const float* p = As + (kk + qd) * 136 + m;
                af[mi][0] = frag_bits<APRE>(p[0]);
                af[mi][1] = frag_bits<APRE>(p[8]);
                af[mi][2] = frag_bits<APRE>(p[4 * 136]);
                af[mi][3] = frag_bits<APRE>(p[4 * 136 + 8]);
            }
        }
    };

    auto loadB = [&](const float* Bs, int ks, unsigned bf[4][2]) {
        const int kk = ks * 8;
#pragma unroll
        for (int ni = 0; ni < 4; ni++) {
            const int n = nb + ni * 8 + g;
            if (BKC) {
                const float* p = Bs + n * 36 + kk + qd;
                bf[ni][0] = frag_bits<BPRE>(p[0]);
                bf[ni][1] = frag_bits<BPRE>(p[4]);
            } else {
                const float* p = Bs + (kk + qd) * 72 + n;
                bf[ni][0] = frag_bits<BPRE>(p[0]);
                bf[ni][1] = frag_bits<BPRE>(p[4 * 72]);
            }
        }
    };

    float acc[2][4][4];
#pragma unroll
    for (int mi = 0; mi < 2; mi++)
#pragma unroll
        for (int ni = 0; ni < 4; ni++)
#pragma unroll
            for (int r = 0; r < 4; r++) acc[mi][ni][r] = 0.f;

    issue(0); CP_COMMIT();
    issue(1); CP_COMMIT();

    for (int c = 0; c < NC; c++) {
        CP_WAIT1();
        __syncthreads();
        const float* As = sm + (c & 1) * STAGE;
        const float* Bs = As + ASTAGE;

        unsigned afd[2][2][4], bfd[2][4][2];
        loadA(As, 0, afd[0]);
        loadB(Bs, 0, bfd[0]);
#pragma unroll
        for (int ks = 0; ks < 4; ks++) {
            const int cur = ks & 1;
            if (ks < 3) {
                loadA(As, ks + 1, afd[cur ^ 1]);
                loadB(Bs, ks + 1, bfd[cur ^ 1]);
            }
#pragma unroll
            for (int mi = 0; mi < 2; mi++)
#pragma unroll
                for (int ni = 0; ni < 4; ni++)
                    mma_tf32(acc[mi][ni], afd[cur][mi], bfd[cur][ni]);
        }

        __syncthreads();
        if (c + 2 < NC) issue(c + 2);
        CP_COMMIT();
    }

#pragma unroll
    for (int mi = 0; mi < 2; mi++)
#pragma unroll
        for (int ni = 0; ni < 4; ni++) {
            const int row = mb + mi * 16 + g;
            const int col = nb + ni * 8 + 2 * qd;
            float v0 = acc[mi][ni][0], v1 = acc[mi][ni][1];
            float v2 = acc[mi][ni][2], v3 = acc[mi][ni][3];
            if (DPRE) {
                v0 = __uint_as_float(f2tf32(v0)); v1 = __uint_as_float(f2tf32(v1));
                v2 = __uint_as_float(f2tf32(v2)); v3 = __uint_as_float(f2tf32(v3));
            }
            *(float2*)&D[(size_t)row * ldd + col]       = make_float2(v0, v1);
            *(float2*)&D[(size_t)(row + 8) * ldd + col] = make_float2(v2, v3);
        }
}

// =============================================================================
// OLD engine (kept for k_out / k_zmat): 128 x NCOLS, 256 thr, 3-stage, occ 2.
// =============================================================================
template<int NCOLS, bool AKC, bool BKC, bool APRE, bool BPRE, bool DPRE>
__device__ __forceinline__ void gemm_cp(const float* __restrict__ A, int lda,
                                        const float* __restrict__ B, int ldb,
                                        unsigned kmaskB,
                                        int NC, float* __restrict__ D, int ldd)
{
    extern __shared__ float sm[];
    constexpr int BPITCH = NCOLS + 8;                     // conflict-free scatter
    constexpr int ASTAGE = AKC ? 128 * 36 : 32 * 136;
    constexpr int BSTAGE = BKC ? NCOLS * 36 : 32 * BPITCH;
    constexpr int STAGE  = ASTAGE + BSTAGE;
    constexpr int NI     = (NCOLS / 2) / 8;               // 8 or 4

    const int tid  = threadIdx.x;
    const int lane = tid & 31;
    const int w    = tid >> 5;
    const int g    = lane >> 2;
    const int qd   = lane & 3;
    const int mb   = (w >> 1) * 32;
    const int nb   = (w & 1) * (NCOLS / 2);

    auto issue = [&](int c) {
        float* stA = sm + (c % 3) * STAGE;
        if (AKC) {
#pragma unroll
            for (int it = 0; it < 4; it++) {
                int i   = tid + it * 256;
                int row = i >> 3, kc = (i & 7) * 4;
                cp16(smem_u32(stA + row * 36 + kc),
                     A + (size_t)row * lda + (size_t)c * 32 + kc);
            }
        } else {
#pragma unroll
            for (int it = 0; it < 4; it++) {
                int i  = tid + it * 256;
                int kr = i >> 5, mc = (i & 31) * 4;
                cp16(smem_u32(stA + kr * 136 + mc),
                     A + (size_t)(c * 32 + kr) * lda + mc);
            }
        }
        float* stB = stA + ASTAGE;
        unsigned koff = ((unsigned)c * 32u) & kmaskB;
        if (BKC) {
#pragma unroll
            for (int it = 0; it < NCOLS / 32; it++) {
                int i   = tid + it * 256;
                int row = i >> 3, kc = (i & 7) * 4;
                cp16(smem_u32(stB + row * 36 + kc),
                     B + (size_t)row * ldb + koff + kc);
            }
        } else {
#pragma unroll
            for (int it = 0; it < NCOLS / 32; it++) {
                int i  = tid + it * 256;
                int kr = i / (NCOLS / 4);
                int nc = (i % (NCOLS / 4)) * 4;
                cp16(smem_u32(stB + (size_t)kr * BPITCH + nc),
                     B + (size_t)(koff + kr) * ldb + nc);
            }
        }
    };

    auto loadA = [&](const float* As, int ks, unsigned af[2][4]) {
        const int kk = ks * 8;
#pragma unroll
        for (int mi = 0; mi < 2; mi++) {
            const int m = mb + mi * 16 + g;
            if (AKC) {
                const float* p = As + m * 36 + kk + qd;
                af[mi][0] = frag_bits<APRE>(p[0]);
                af[mi][1] = frag_bits<APRE>(p[8 * 36]);
                af[mi][2] = frag_bits<APRE>(p[4]);
                af[mi][3] = frag_bits<APRE>(p[8 * 36 + 4]);
            } else {
                const float* p = As + (kk + qd) * 136 + m;
                af[mi][0] = frag_bits<APRE>(p[0]);
                af[mi][1] = frag_bits<APRE>(p[8]);
                af[mi][2] = frag_bits<APRE>(p[4 * 136]);
                af[mi][3] = frag_bits<APRE>(p[4 * 136 + 8]);
            }
        }
    };

    float acc[2][NI][4];
#pragma unroll
    for (int mi = 0; mi < 2; mi++)
#pragma unroll
        for (int ni = 0; ni < NI; ni++)
#pragma unroll
            for (int r = 0; r < 4; r++) acc[mi][ni][r] = 0.f;

    issue(0); CP_COMMIT();
    issue(1); CP_COMMIT();

    for (int c = 0; c < NC; c++) {
        CP_WAIT1();
        __syncthreads();
        const float* As = sm + (c % 3) * STAGE;
        const float* Bs = As + ASTAGE;

        unsigned afd[2][2][4];
        loadA(As, 0, afd[0]);
#pragma unroll
        for (int ks = 0; ks < 4; ks++) {
            const int cur = ks & 1;
            if (ks < 3) loadA(As, ks + 1, afd[cur ^ 1]);
            const int kk = ks * 8;
            unsigned bf[NI][2];
#pragma unroll
            for (int ni = 0; ni < NI; ni++) {
                const int n = nb + ni * 8 + g;
                if (BKC) {
                    const float* p = Bs + n * 36 + kk + qd;
                    bf[ni][0] = frag_bits<BPRE>(p[0]);
                    bf[ni][1] = frag_bits<BPRE>(p[4]);
                } else {
                    const float* p = Bs + (kk + qd) * BPITCH + n;
                    bf[ni][0] = frag_bits<BPRE>(p[0]);
                    bf[ni][1] = frag_bits<BPRE>(p[4 * BPITCH]);
                }
            }
#pragma unroll
            for (int mi = 0; mi < 2; mi++)
#pragma unroll
                for (int ni = 0; ni < NI; ni++)
                    mma_tf32(acc[mi][ni], afd[cur][mi], bf[ni]);
        }

        if (c + 2 < NC) issue(c + 2);
        CP_COMMIT();
    }

#pragma unroll
    for (int mi = 0; mi < 2; mi++)
#pragma unroll
        for (int ni = 0; ni < NI; ni++) {
            const int row = mb + mi * 16 + g;
            const int col = nb + ni * 8 + 2 * qd;
            float v0 = acc[mi][ni][0], v1 = acc[mi][ni][1];
            float v2 = acc[mi][ni][2], v3 = acc[mi][ni][3];
            if (DPRE) {
                v0 = __uint_as_float(f2tf32(v0)); v1 = __uint_as_float(f2tf32(v1));
                v2 = __uint_as_float(f2tf32(v2)); v3 = __uint_as_float(f2tf32(v3));
            }
            *(float2*)&D[(size_t)row * ldd + col]       = make_float2(v0, v1);
            *(float2*)&D[(size_t)(row + 8) * ldd + col] = make_float2(v2, v3);
        }
}

// =============================================================================
// K1: P half: g_Pd[b][t][ph*512+s] = sum_{c in half ph} q[b][c][t] k[b][c][s]
// New engine 128x64 tiles, split-K=2 -> grid 8x4x16 = 512 CTAs, occ 3.
// =============================================================================
__global__ void __launch_bounds__(256, 3) k_pmat(const float* __restrict__ q,
                                                 const float* __restrict__ kk_)
{
    const int z  = blockIdx.z;
    const int b  = z >> 1;
    const int ph = z & 1;
    const int t0 = blockIdx.y * 128;
    const int s0 = blockIdx.x * 64;
    const float* Ab = q   + (size_t)b * CDIM * TDIM + (size_t)ph * (CDIM / 2) * TDIM + t0;
    const float* Bb = kk_ + (size_t)b * CDIM * TDIM + (size_t)ph * (CDIM / 2) * TDIM + s0;
    float* D = g_Pd + (size_t)b * TDIM * 1024 + (size_t)t0 * 1024 + ph * 512 + s0;
    gemm_db<false, false, false, false, true>(
        Ab, TDIM, Bb, TDIM, 0x7fffffffu, (CDIM / 2) / 32, D, 1024);
}

// =============================================================================
// K2a: U[b,h][t][e] = sum_{k'=0..1023} g_Pd[b][t][k'] * Wk[h][e][k' mod 512]
// New engine, grid 4x8x8 = 256 CTAs.
// =============================================================================
__global__ void __launch_bounds__(256, 3) k_umat(const float* __restrict__ Wk)
{
    const int b  = blockIdx.z;
    const int h  = blockIdx.y;
    const int t0 = blockIdx.x * 128;
    const float* Ab = g_Pd + (size_t)b * TDIM * 1024 + (size_t)t0 * 1024;
    const float* Bb = Wk + (size_t)h * HDIM * TDIM;
    float* D = g_U + (size_t)(b * NH + h) * TDIM * HDIM + (size_t)t0 * HDIM;
    gemm_db<true, true, true, false, false>(
        Ab, 1024, Bb, TDIM, 511u, 1024 / 32, D, HDIM);
}

// =============================================================================
// K2b: per (b,h): S = Wq_h @ U / sqrt(512); W = softmax_rows(S);
// store W^T (tf32-pre-rounded) -> g_W[bh][e][d]
// =============================================================================
__global__ void __launch_bounds__(256) k_attn(const float* __restrict__ Wq)
{
    const int bh = blockIdx.x;
    const int h = bh & 7;

    __shared__ float Ws[64][65];
    __shared__ float Us[32][68];
    __shared__ float Wqs[64][33];

    const float* Ub  = g_U + (size_t)bh * TDIM * HDIM;
    const float* Wqh = Wq + (size_t)h * HDIM * TDIM;

    const int tid = threadIdx.x;
    const int tx = tid & 15, ty = tid >> 4;

    float acc[4][4];
#pragma unroll
    for (int m = 0; m < 4; m++)
#pragma unroll
        for (int n = 0; n < 4; n++) acc[m][n] = 0.f;

    for (int t0 = 0; t0 < TDIM; t0 += 32) {
#pragma unroll
        for (int i = 0; i < 2; i++) {
            int idx = tid + i * 256;
            int tl  = idx >> 4;
            int eq  = (idx & 15) * 4;
            *(float4*)&Us[tl][eq] = *(const float4*)&Ub[(size_t)(t0 + tl) * HDIM + eq];
        }
#pragma unroll
        for (int i = 0; i < 2; i++) {
            int idx = tid + i * 256;
            int d   = idx >> 3;
            int tq  = (idx & 7) * 4;
            float4 a = *(const float4*)&Wqh[(size_t)d * TDIM + t0 + tq];
            Wqs[d][tq + 0] = a.x; Wqs[d][tq + 1] = a.y;
            Wqs[d][tq + 2] = a.z; Wqs[d][tq + 3] = a.w;
        }
        __syncthreads();
#pragma unroll
        for (int tl = 0; tl < 32; tl++) {
            float ra[4], rb[4];
#pragma unroll
            for (int m = 0; m < 4; m++) ra[m] = Wqs[ty * 4 + m][tl];
#pragma unroll
            for (int n = 0; n < 4; n++) rb[n] = Us[tl][tx * 4 + n];
#pragma unroll
            for (int m = 0; m < 4; m++)
#pragma unroll
                for (int n = 0; n < 4; n++) acc[m][n] += ra[m] * rb[n];
        }
        __syncthreads();
    }

#pragma unroll
    for (int m = 0; m < 4; m++)
#pragma unroll
        for (int n = 0; n < 4; n++)
            Ws[ty * 4 + m][tx * 4 + n] = acc[m][n] * SCALE_INV;
    __syncthreads();

    if (tid < 64) {
        float mx = -1e30f;
#pragma unroll 8
        for (int e = 0; e < 64; e++) mx = fmaxf(mx, Ws[tid][e]);
        float sum = 0.f;
#pragma unroll 8
        for (int e = 0; e < 64; e++) { float ex = expf(Ws[tid][e] - mx); Ws[tid][e] = ex; sum += ex; }
        float inv = 1.f / sum;
#pragma unroll 8
        for (int e = 0; e < 64; e++) Ws[tid][e] *= inv;
    }
    __syncthreads();

    float* Wt = g_W + (size_t)bh * HDIM * HDIM;
    for (int idx = tid; idx < HDIM * HDIM; idx += 256) {
        int e = idx >> 6, d = idx & 63;
        Wt[(size_t)e * HDIM + d] = __uint_as_float(f2tf32(Ws[d][e]));
    }
}

// =============================================================================
// K2c: Z[b][o][h*64+e] = sum_d Wo[o][h*64+d] * W_h[d][e]
// Old engine, grid (4 o-chunks x 64 bh) = 256 CTAs.
// =============================================================================
__global__ void __launch_bounds__(256, 2) k_zmat(const float* __restrict__ Wo)
{
    const int bh = blockIdx.y;
    const int b = bh >> 3, h = bh & 7;
    const int o0 = blockIdx.x * 128;
    const float* Ab = Wo + (size_t)o0 * (NH * HDIM) + h * HDIM;
    const float* Bb = g_W + (size_t)bh * HDIM * HDIM;
    float* D = g_Z + (size_t)b * TDIM * TDIM + (size_t)o0 * TDIM + h * HDIM;
    gemm_cp<64, true, true, false, true, true>(
        Ab, NH * HDIM, Bb, HDIM, 0x7fffffffu, HDIM / 32, D, TDIM);
}

// =============================================================================
// K3: G[b][o][t] = sum_j Z[b][o][j] * Wv_flat[j][t]
// New engine, grid 8x4x8 = 256 CTAs.
// =============================================================================
__global__ void __launch_bounds__(256, 3) k_gmat(const float* __restrict__ Wv)
{
    const int b  = blockIdx.z;
    const int o0 = blockIdx.y * 128;
    const int t0 = blockIdx.x * 64;
    const float* Ab = g_Z + (size_t)b * TDIM * TDIM + (size_t)o0 * TDIM;
    const float* Bb = Wv + t0;
    float* D = g_G + (size_t)b * TDIM * TDIM + (size_t)o0 * TDIM + t0;
    gemm_db<true, false, true, false, true>(
        Ab, TDIM, Bb, TDIM, 0x7fffffffu, TDIM / 32, D, TDIM);
}

// =============================================================================
// K4: out[b][c][o] = sum_t v[b][c][t] * G[b][o][t]  (old engine, 128x128)
// =============================================================================
__global__ void __launch_bounds__(256, 2) k_out(const float* __restrict__ v,
                                                float* __restrict__ out)
{
    const int b  = blockIdx.z;
    const int c0 = blockIdx.y * 128;
    const int o0 = blockIdx.x * 128;
    const float* Ab = v + (size_t)b * CDIM * TDIM + (size_t)c0 * TDIM;
    const float* Bb = g_G + (size_t)b * TDIM * TDIM + (size_t)o0 * TDIM;
    float* D = out + (size_t)b * CDIM * ODIM + (size_t)c0 * ODIM + o0;
    gemm_cp<128, true, true, false, true, false>(
        Ab, TDIM, Bb, TDIM, 0x7fffffffu, TDIM / 32, D, ODIM);
}

// =============================================================================
extern "C" void kernel_launch(void* const* d_in, const int* in_sizes, int n_in,
                              void* d_out, int out_size)
{
    const float* q  = (const float*)d_in[0];
    const float* k  = (const float*)d_in[1];
    const float* v  = (const float*)d_in[2];
    const float* Wq = (const float*)d_in[3];
    const float* Wk = (const float*)d_in[4];
    const float* Wv = (const float*)d_in[5];
    const float* Wo = (const float*)d_in[6];
    float* out = (float*)d_out;
    (void)in_sizes; (void)n_in; (void)out_size;

    // new engine: 2 stages * (ASTAGE + BSTAGE) * 4 bytes
    const int SM_PMAT = 2 * (32 * 136 + 32 * 72) * 4;     //  53248
    const int SM_UMAT = 2 * (128 * 36 + 64 * 36) * 4;     //  55296
    const int SM_GMAT = 2 * (128 * 36 + 32 * 72) * 4;     //  55296
    // old engine: 3 stages
    const int SM_ZMAT = 3 * (128 * 36 + 64 * 36) * 4;     //  82944
    const int SM_OUT  = 3 * (128 * 36 + 128 * 36) * 4;    // 110592

    cudaFuncSetAttribute(k_pmat, cudaFuncAttributeMaxDynamicSharedMemorySize, SM_PMAT);
    cudaFuncSetAttribute(k_umat, cudaFuncAttributeMaxDynamicSharedMemorySize, SM_UMAT);
    cudaFuncSetAttribute(k_zmat, cudaFuncAttributeMaxDynamicSharedMemorySize, SM_ZMAT);
    cudaFuncSetAttribute(k_gmat, cudaFuncAttributeMaxDynamicSharedMemorySize, SM_GMAT);
    cudaFuncSetAttribute(k_out,  cudaFuncAttributeMaxDynamicSharedMemorySize, SM_OUT);

    k_pmat<<<dim3(8, 4, BSZ * 2), 256, SM_PMAT>>>(q, k);
    k_umat<<<dim3(4, NH, BSZ),    256, SM_UMAT>>>(Wk);
    k_attn<<<BSZ * NH,            256>>>(Wq);
    k_zmat<<<dim3(4, BSZ * NH),   256, SM_ZMAT>>>(Wo);
    k_gmat<<<dim3(8, 4, BSZ),     256, SM_GMAT>>>(Wv);
    k_out <<<dim3(4, 32, BSZ),    256, SM_OUT>>>(v, out);
}

// round 9
// speedup vs baseline: 1.0696x; 1.0696x over previous
#include <cuda_runtime.h>
#include <cstdint>
#include <math.h>

// Problem constants
#define BSZ  8
#define CDIM 4096
#define TDIM 512
#define NH   8
#define HDIM 64
#define ODIM 512
#define SCALE_INV (1.0f / 22.62741699796952f)   // 1/sqrt(512)

// ---------------- scratch (static device globals; allocation-free) ----------
// g_Pd[b][t][1024]: cols 0-511 = K-half-0 partial of P, 512-1023 = half-1.
// (tf32-pre-rounded)  U = (P0+P1)@Wk^T == [P0|P1] @ [Wk|Wk]^T over K=1024.
__device__ __align__(256) float g_Pd[BSZ * TDIM * 1024];
__device__ __align__(256) float g_U [BSZ * NH * TDIM * HDIM];
__device__ __align__(256) float g_W [BSZ * NH * HDIM * HDIM];  // W^T, tf32-pre-rounded
__device__ __align__(256) float g_Z [BSZ * TDIM * TDIM];       // tf32-pre-rounded
__device__ __align__(256) float g_G [BSZ * TDIM * TDIM];       // tf32-pre-rounded

// ---------------- helpers ----------------
__device__ __forceinline__ unsigned f2tf32(float x) {
    unsigned r;
    asm("cvt.rna.tf32.f32 %0, %1;" : "=r"(r) : "f"(x));
    return r;
}

template<bool PRE>
__device__ __forceinline__ unsigned frag_bits(float x) {
    return PRE ? __float_as_uint(x) : f2tf32(x);
}

__device__ __forceinline__ uint32_t smem_u32(const void* p) {
    uint32_t a;
    asm("{ .reg .u64 t; cvta.to.shared.u64 t, %1; cvt.u32.u64 %0, t; }" : "=r"(a) : "l"(p));
    return a;
}

__device__ __forceinline__ void cp16(uint32_t dst, const float* src) {
    asm volatile("cp.async.cg.shared.global [%0], [%1], 16;" :: "r"(dst), "l"(src));
}
#define CP_COMMIT() asm volatile("cp.async.commit_group;" ::: "memory")
#define CP_WAIT1()  asm volatile("cp.async.wait_group 1;"  ::: "memory")

__device__ __forceinline__ void mma_tf32(float* c, const unsigned* a, const unsigned* b) {
    asm("mma.sync.aligned.m16n8k8.row.col.f32.tf32.tf32.f32 "
        "{%0,%1,%2,%3},{%4,%5,%6,%7},{%8,%9},{%0,%1,%2,%3};"
        : "+f"(c[0]), "+f"(c[1]), "+f"(c[2]), "+f"(c[3])
        : "r"(a[0]), "r"(a[1]), "r"(a[2]), "r"(a[3]),
          "r"(b[0]), "r"(b[1]));
}

// =============================================================================
// 128x64 engine: BK=32, 256 thr (8 warps = 4M x 2N, warp tile 32x32), 2-stage
// cp.async, both fragment operands double-buffered, conflict-free pitches,
// occupancy 3.  (Used by k_umat / k_gmat.)
// =============================================================================
template<bool AKC, bool BKC, bool APRE, bool BPRE, bool DPRE>
__device__ __forceinline__ void gemm_db(const float* __restrict__ A, int lda,
                                        const float* __restrict__ B, int ldb,
                                        unsigned kmaskB,
                                        int NC, float* __restrict__ D, int ldd)
{
    extern __shared__ float sm[];
    constexpr int ASTAGE = AKC ? 128 * 36 : 32 * 136;
    constexpr int BSTAGE = BKC ? 64 * 36 : 32 * 72;
    constexpr int STAGE  = ASTAGE + BSTAGE;

    const int tid  = threadIdx.x;
    const int lane = tid & 31;
    const int w    = tid >> 5;
    const int g    = lane >> 2;
    const int qd   = lane & 3;
    const int mb   = (w & 3) * 32;
    const int nb   = (w >> 2) * 32;

    auto issue = [&](int c) {
        float* stA = sm + (c & 1) * STAGE;
        if (AKC) {
#pragma unroll
            for (int it = 0; it < 4; it++) {
                int i   = tid + it * 256;
                int row = i >> 3, kc = (i & 7) * 4;
                cp16(smem_u32(stA + row * 36 + kc),
                     A + (size_t)row * lda + (size_t)c * 32 + kc);
            }
        } else {
#pragma unroll
            for (int it = 0; it < 4; it++) {
                int i  = tid + it * 256;
                int kr = i >> 5, mc = (i & 31) * 4;
                cp16(smem_u32(stA + kr * 136 + mc),
                     A + (size_t)(c * 32 + kr) * lda + mc);
            }
        }
        float* stB = stA + ASTAGE;
        unsigned koff = ((unsigned)c * 32u) & kmaskB;
        if (BKC) {
#pragma unroll
            for (int it = 0; it < 2; it++) {
                int i   = tid + it * 256;
                int row = i >> 3, kc = (i & 7) * 4;
                cp16(smem_u32(stB + row * 36 + kc),
                     B + (size_t)row * ldb + koff + kc);
            }
        } else {
#pragma unroll
            for (int it = 0; it < 2; it++) {
                int i  = tid + it * 256;
                int kr = i >> 4, nc = (i & 15) * 4;
                cp16(smem_u32(stB + kr * 72 + nc),
                     B + (size_t)(koff + kr) * ldb + nc);
            }
        }
    };

    auto loadA = [&](const float* As, int ks, unsigned af[2][4]) {
        const int kk = ks * 8;
#pragma unroll
        for (int mi = 0; mi < 2; mi++) {
            const int m = mb + mi * 16 + g;
            if (AKC) {
                const float* p = As + m * 36 + kk + qd;
                af[mi][0] = frag_bits<APRE>(p[0]);
                af[mi][1] = frag_bits<APRE>(p[8 * 36]);
                af[mi][2] = frag_bits<APRE>(p[4]);
                af[mi][3] = frag_bits<APRE>(p[8 * 36 + 4]);
            } else {
                const float* p = As + (kk + qd) * 136 + m;
                af[mi][0] = frag_bits<APRE>(p[0]);
                af[mi][1] = frag_bits<APRE>(p[8]);
                af[mi][2] = frag_bits<APRE>(p[4 * 136]);
                af[mi][3] = frag_bits<APRE>(p[4 * 136 + 8]);
            }
        }
    };

    auto loadB = [&](const float* Bs, int ks, unsigned bf[4][2]) {
        const int kk = ks * 8;
#pragma unroll
        for (int ni = 0; ni < 4; ni++) {
            const int n = nb + ni * 8 + g;
            if (BKC) {
                const float* p = Bs + n * 36 + kk + qd;
                bf[ni][0] = frag_bits<BPRE>(p[0]);
                bf[ni][1] = frag_bits<BPRE>(p[4]);
            } else {
                const float* p = Bs + (kk + qd) * 72 + n;
                bf[ni][0] = frag_bits<BPRE>(p[0]);
                bf[ni][1] = frag_bits<BPRE>(p[4 * 72]);
            }
        }
    };

    float acc[2][4][4];
#pragma unroll
    for (int mi = 0; mi < 2; mi++)
#pragma unroll
        for (int ni = 0; ni < 4; ni++)
#pragma unroll
            for (int r = 0; r < 4; r++) acc[mi][ni][r] = 0.f;

    issue(0); CP_COMMIT();
    issue(1); CP_COMMIT();

    for (int c = 0; c < NC; c++) {
        CP_WAIT1();
        __syncthreads();
        const float* As = sm + (c & 1) * STAGE;
        const float* Bs = As + ASTAGE;

        unsigned afd[2][2][4], bfd[2][4][2];
        loadA(As, 0, afd[0]);
        loadB(Bs, 0, bfd[0]);
#pragma unroll
        for (int ks = 0; ks < 4; ks++) {
            const int cur = ks & 1;
            if (ks < 3) {
                loadA(As, ks + 1, afd[cur ^ 1]);
                loadB(Bs, ks + 1, bfd[cur ^ 1]);
            }
#pragma unroll
            for (int mi = 0; mi < 2; mi++)
#pragma unroll
                for (int ni = 0; ni < 4; ni++)
                    mma_tf32(acc[mi][ni], afd[cur][mi], bfd[cur][ni]);
        }

        __syncthreads();
        if (c + 2 < NC) issue(c + 2);
        CP_COMMIT();
    }

#pragma unroll
    for (int mi = 0; mi < 2; mi++)
#pragma unroll
        for (int ni = 0; ni < 4; ni++) {
            const int row = mb + mi * 16 + g;
            const int col = nb + ni * 8 + 2 * qd;
            float v0 = acc[mi][ni][0], v1 = acc[mi][ni][1];
            float v2 = acc[mi][ni][2], v3 = acc[mi][ni][3];
            if (DPRE) {
                v0 = __uint_as_float(f2tf32(v0)); v1 = __uint_as_float(f2tf32(v1));
                v2 = __uint_as_float(f2tf32(v2)); v3 = __uint_as_float(f2tf32(v3));
            }
            *(float2*)&D[(size_t)row * ldd + col]       = make_float2(v0, v1);
            *(float2*)&D[(size_t)(row + 8) * ldd + col] = make_float2(v2, v3);
        }
}

// =============================================================================
// 128 x NCOLS engine: 256 thr, 3-stage cp.async, conflict-free pitches
// (A-scatter 136, B-scatter NCOLS+8), occ 2.  (k_pmat / k_zmat / k_out.)
// =============================================================================
template<int NCOLS, bool AKC, bool BKC, bool APRE, bool BPRE, bool DPRE>
__device__ __forceinline__ void gemm_cp(const float* __restrict__ A, int lda,
                                        const float* __restrict__ B, int ldb,
                                        unsigned kmaskB,
                                        int NC, float* __restrict__ D, int ldd)
{
    extern __shared__ float sm[];
    constexpr int BPITCH = NCOLS + 8;                     // conflict-free scatter
    constexpr int ASTAGE = AKC ? 128 * 36 : 32 * 136;
    constexpr int BSTAGE = BKC ? NCOLS * 36 : 32 * BPITCH;
    constexpr int STAGE  = ASTAGE + BSTAGE;
    constexpr int NI     = (NCOLS / 2) / 8;               // 8 or 4

    const int tid  = threadIdx.x;
    const int lane = tid & 31;
    const int w    = tid >> 5;
    const int g    = lane >> 2;
    const int qd   = lane & 3;
    const int mb   = (w >> 1) * 32;
    const int nb   = (w & 1) * (NCOLS / 2);

    auto issue = [&](int c) {
        float* stA = sm + (c % 3) * STAGE;
        if (AKC) {
#pragma unroll
            for (int it = 0; it < 4; it++) {
                int i   = tid + it * 256;
                int row = i >> 3, kc = (i & 7) * 4;
                cp16(smem_u32(stA + row * 36 + kc),
                     A + (size_t)row * lda + (size_t)c * 32 + kc);
            }
        } else {
#pragma unroll
            for (int it = 0; it < 4; it++) {
                int i  = tid + it * 256;
                int kr = i >> 5, mc = (i & 31) * 4;
                cp16(smem_u32(stA + kr * 136 + mc),
                     A + (size_t)(c * 32 + kr) * lda + mc);
            }
        }
        float* stB = stA + ASTAGE;
        unsigned koff = ((unsigned)c * 32u) & kmaskB;
        if (BKC) {
#pragma unroll
            for (int it = 0; it < NCOLS / 32; it++) {
                int i   = tid + it * 256;
                int row = i >> 3, kc = (i & 7) * 4;
                cp16(smem_u32(stB + row * 36 + kc),
                     B + (size_t)row * ldb + koff + kc);
            }
        } else {
#pragma unroll
            for (int it = 0; it < NCOLS / 32; it++) {
                int i  = tid + it * 256;
                int kr = i / (NCOLS / 4);
                int nc = (i % (NCOLS / 4)) * 4;
                cp16(smem_u32(stB + (size_t)kr * BPITCH + nc),
                     B + (size_t)(koff + kr) * ldb + nc);
            }
        }
    };

    auto loadA = [&](const float* As, int ks, unsigned af[2][4]) {
        const int kk = ks * 8;
#pragma unroll
        for (int mi = 0; mi < 2; mi++) {
            const int m = mb + mi * 16 + g;
            if (AKC) {
                const float* p = As + m * 36 + kk + qd;
                af[mi][0] = frag_bits<APRE>(p[0]);
                af[mi][1] = frag_bits<APRE>(p[8 * 36]);
                af[mi][2] = frag_bits<APRE>(p[4]);
                af[mi][3] = frag_bits<APRE>(p[8 * 36 + 4]);
            } else {
                const float* p = As + (kk + qd) * 136 + m;
                af[mi][0] = frag_bits<APRE>(p[0]);
                af[mi][1] = frag_bits<APRE>(p[8]);
                af[mi][2] = frag_bits<APRE>(p[4 * 136]);
                af[mi][3] = frag_bits<APRE>(p[4 * 136 + 8]);
            }
        }
    };

    float acc[2][NI][4];
#pragma unroll
    for (int mi = 0; mi < 2; mi++)
#pragma unroll
        for (int ni = 0; ni < NI; ni++)
#pragma unroll
            for (int r = 0; r < 4; r++) acc[mi][ni][r] = 0.f;

    issue(0); CP_COMMIT();
    issue(1); CP_COMMIT();

    for (int c = 0; c < NC; c++) {
        CP_WAIT1();
        __syncthreads();
        const float* As = sm + (c % 3) * STAGE;
        const float* Bs = As + ASTAGE;

        unsigned afd[2][2][4];
        loadA(As, 0, afd[0]);
#pragma unroll
        for (int ks = 0; ks < 4; ks++) {
            const int cur = ks & 1;
            if (ks < 3) loadA(As, ks + 1, afd[cur ^ 1]);
            const int kk = ks * 8;
            unsigned bf[NI][2];
#pragma unroll
            for (int ni = 0; ni < NI; ni++) {
                const int n = nb + ni * 8 + g;
                if (BKC) {
                    const float* p = Bs + n * 36 + kk + qd;
                    bf[ni][0] = frag_bits<BPRE>(p[0]);
                    bf[ni][1] = frag_bits<BPRE>(p[4]);
                } else {
                    const float* p = Bs + (kk + qd) * BPITCH + n;
                    bf[ni][0] = frag_bits<BPRE>(p[0]);
                    bf[ni][1] = frag_bits<BPRE>(p[4 * BPITCH]);
                }
            }
#pragma unroll
            for (int mi = 0; mi < 2; mi++)
#pragma unroll
                for (int ni = 0; ni < NI; ni++)
                    mma_tf32(acc[mi][ni], afd[cur][mi], bf[ni]);
        }

        if (c + 2 < NC) issue(c + 2);
        CP_COMMIT();
    }

#pragma unroll
    for (int mi = 0; mi < 2; mi++)
#pragma unroll
        for (int ni = 0; ni < NI; ni++) {
            const int row = mb + mi * 16 + g;
            const int col = nb + ni * 8 + 2 * qd;
            float v0 = acc[mi][ni][0], v1 = acc[mi][ni][1];
            float v2 = acc[mi][ni][2], v3 = acc[mi][ni][3];
            if (DPRE) {
                v0 = __uint_as_float(f2tf32(v0)); v1 = __uint_as_float(f2tf32(v1));
                v2 = __uint_as_float(f2tf32(v2)); v3 = __uint_as_float(f2tf32(v3));
            }
            *(float2*)&D[(size_t)row * ldd + col]       = make_float2(v0, v1);
            *(float2*)&D[(size_t)(row + 8) * ldd + col] = make_float2(v2, v3);
        }
}

// =============================================================================
// K1: P half: g_Pd[b][t][ph*512+s] = sum_{c in half ph} q[b][c][t] k[b][c][s]
// 128x128 engine (conflict-free pitches), split-K=2 -> grid 4x4x16 = 256, occ 2.
// =============================================================================
__global__ void __launch_bounds__(256, 2) k_pmat(const float* __restrict__ q,
                                                 const float* __restrict__ kk_)
{
    const int z  = blockIdx.z;
    const int b  = z >> 1;
    const int ph = z & 1;
    const int t0 = blockIdx.y * 128;
    const int s0 = blockIdx.x * 128;
    const float* Ab = q   + (size_t)b * CDIM * TDIM + (size_t)ph * (CDIM / 2) * TDIM + t0;
    const float* Bb = kk_ + (size_t)b * CDIM * TDIM + (size_t)ph * (CDIM / 2) * TDIM + s0;
    float* D = g_Pd + (size_t)b * TDIM * 1024 + (size_t)t0 * 1024 + ph * 512 + s0;
    gemm_cp<128, false, false, false, false, true>(
        Ab, TDIM, Bb, TDIM, 0x7fffffffu, (CDIM / 2) / 32, D, 1024);
}

// =============================================================================
// K2a: U[b,h][t][e] = sum_{k'=0..1023} g_Pd[b][t][k'] * Wk[h][e][k' mod 512]
// =============================================================================
__global__ void __launch_bounds__(256, 3) k_umat(const float* __restrict__ Wk)
{
    const int b  = blockIdx.z;
    const int h  = blockIdx.y;
    const int t0 = blockIdx.x * 128;
    const float* Ab = g_Pd + (size_t)b * TDIM * 1024 + (size_t)t0 * 1024;
    const float* Bb = Wk + (size_t)h * HDIM * TDIM;
    float* D = g_U + (size_t)(b * NH + h) * TDIM * HDIM + (size_t)t0 * HDIM;
    gemm_db<true, true, true, false, false>(
        Ab, 1024, Bb, TDIM, 511u, 1024 / 32, D, HDIM);
}

// =============================================================================
// K2b: per (b,h): S = Wq_h @ U / sqrt(512); W = softmax_rows(S);
// store W^T (tf32-pre-rounded) -> g_W[bh][e][d]
// =============================================================================
__global__ void __launch_bounds__(256) k_attn(const float* __restrict__ Wq)
{
    const int bh = blockIdx.x;
    const int h = bh & 7;

    __shared__ float Ws[64][65];
    __shared__ float Us[32][68];
    __shared__ float Wqs[64][33];

    const float* Ub  = g_U + (size_t)bh * TDIM * HDIM;
    const float* Wqh = Wq + (size_t)h * HDIM * TDIM;

    const int tid = threadIdx.x;
    const int tx = tid & 15, ty = tid >> 4;

    float acc[4][4];
#pragma unroll
    for (int m = 0; m < 4; m++)
#pragma unroll
        for (int n = 0; n < 4; n++) acc[m][n] = 0.f;

    for (int t0 = 0; t0 < TDIM; t0 += 32) {
#pragma unroll
        for (int i = 0; i < 2; i++) {
            int idx = tid + i * 256;
            int tl  = idx >> 4;
            int eq  = (idx & 15) * 4;
            *(float4*)&Us[tl][eq] = *(const float4*)&Ub[(size_t)(t0 + tl) * HDIM + eq];
        }
#pragma unroll
        for (int i = 0; i < 2; i++) {
            int idx = tid + i * 256;
            int d   = idx >> 3;
            int tq  = (idx & 7) * 4;
            float4 a = *(const float4*)&Wqh[(size_t)d * TDIM + t0 + tq];
            Wqs[d][tq + 0] = a.x; Wqs[d][tq + 1] = a.y;
            Wqs[d][tq + 2] = a.z; Wqs[d][tq + 3] = a.w;
        }
        __syncthreads();
#pragma unroll
        for (int tl = 0; tl < 32; tl++) {
            float ra[4], rb[4];
#pragma unroll
            for (int m = 0; m < 4; m++) ra[m] = Wqs[ty * 4 + m][tl];
#pragma unroll
            for (int n = 0; n < 4; n++) rb[n] = Us[tl][tx * 4 + n];
#pragma unroll
            for (int m = 0; m < 4; m++)
#pragma unroll
                for (int n = 0; n < 4; n++) acc[m][n] += ra[m] * rb[n];
        }
        __syncthreads();
    }

#pragma unroll
    for (int m = 0; m < 4; m++)
#pragma unroll
        for (int n = 0; n < 4; n++)
            Ws[ty * 4 + m][tx * 4 + n] = acc[m][n] * SCALE_INV;
    __syncthreads();

    if (tid < 64) {
        float mx = -1e30f;
#pragma unroll 8
        for (int e = 0; e < 64; e++) mx = fmaxf(mx, Ws[tid][e]);
        float sum = 0.f;
#pragma unroll 8
        for (int e = 0; e < 64; e++) { float ex = expf(Ws[tid][e] - mx); Ws[tid][e] = ex; sum += ex; }
        float inv = 1.f / sum;
#pragma unroll 8
        for (int e = 0; e < 64; e++) Ws[tid][e] *= inv;
    }
    __syncthreads();

    float* Wt = g_W + (size_t)bh * HDIM * HDIM;
    for (int idx = tid; idx < HDIM * HDIM; idx += 256) {
        int e = idx >> 6, d = idx & 63;
        Wt[(size_t)e * HDIM + d] = __uint_as_float(f2tf32(Ws[d][e]));
    }
}

// =============================================================================
// K2c: Z[b][o][h*64+e] = sum_d Wo[o][h*64+d] * W_h[d][e]
// =============================================================================
__global__ void __launch_bounds__(256, 2) k_zmat(const float* __restrict__ Wo)
{
    const int bh = blockIdx.y;
    const int b = bh >> 3, h = bh & 7;
    const int o0 = blockIdx.x * 128;
    const float* Ab = Wo + (size_t)o0 * (NH * HDIM) + h * HDIM;
    const float* Bb = g_W + (size_t)bh * HDIM * HDIM;
    float* D = g_Z + (size_t)b * TDIM * TDIM + (size_t)o0 * TDIM + h * HDIM;
    gemm_cp<64, true, true, false, true, true>(
        Ab, NH * HDIM, Bb, HDIM, 0x7fffffffu, HDIM / 32, D, TDIM);
}

// =============================================================================
// K3: G[b][o][t] = sum_j Z[b][o][j] * Wv_flat[j][t]
// =============================================================================
__global__ void __launch_bounds__(256, 3) k_gmat(const float* __restrict__ Wv)
{
    const int b  = blockIdx.z;
    const int o0 = blockIdx.y * 128;
    const int t0 = blockIdx.x * 64;
    const float* Ab = g_Z + (size_t)b * TDIM * TDIM + (size_t)o0 * TDIM;
    const float* Bb = Wv + t0;
    float* D = g_G + (size_t)b * TDIM * TDIM + (size_t)o0 * TDIM + t0;
    gemm_db<true, false, true, false, true>(
        Ab, TDIM, Bb, TDIM, 0x7fffffffu, TDIM / 32, D, TDIM);
}

// =============================================================================
// K4: out[b][c][o] = sum_t v[b][c][t] * G[b][o][t]
// =============================================================================
__global__ void __launch_bounds__(256, 2) k_out(const float* __restrict__ v,
                                                float* __restrict__ out)
{
    const int b  = blockIdx.z;
    const int c0 = blockIdx.y * 128;
    const int o0 = blockIdx.x * 128;
    const float* Ab = v + (size_t)b * CDIM * TDIM + (size_t)c0 * TDIM;
    const float* Bb = g_G + (size_t)b * TDIM * TDIM + (size_t)o0 * TDIM;
    float* D = out + (size_t)b * CDIM * ODIM + (size_t)c0 * ODIM + o0;
    gemm_cp<128, true, true, false, true, false>(
        Ab, TDIM, Bb, TDIM, 0x7fffffffu, TDIM / 32, D, ODIM);
}

// =============================================================================
extern "C" void kernel_launch(void* const* d_in, const int* in_sizes, int n_in,
                              void* d_out, int out_size)
{
    const float* q  = (const float*)d_in[0];
    const float* k  = (const float*)d_in[1];
    const float* v  = (const float*)d_in[2];
    const float* Wq = (const float*)d_in[3];
    const float* Wk = (const float*)d_in[4];
    const float* Wv = (const float*)d_in[5];
    const float* Wo = (const float*)d_in[6];
    float* out = (float*)d_out;
    (void)in_sizes; (void)n_in; (void)out_size;

    // pmat: 3 stages * (A 32*136 + B 32*136) * 4 bytes
    const int SM_PMAT = 3 * (32 * 136 + 32 * 136) * 4;    // 104448
    const int SM_UMAT = 2 * (128 * 36 + 64 * 36) * 4;     //  55296
    const int SM_GMAT = 2 * (128 * 36 + 32 * 72) * 4;     //  55296
    const int SM_ZMAT = 3 * (128 * 36 + 64 * 36) * 4;     //  82944
    const int SM_OUT  = 3 * (128 * 36 + 128 * 36) * 4;    // 110592

    cudaFuncSetAttribute(k_pmat, cudaFuncAttributeMaxDynamicSharedMemorySize, SM_PMAT);
    cudaFuncSetAttribute(k_umat, cudaFuncAttributeMaxDynamicSharedMemorySize, SM_UMAT);
    cudaFuncSetAttribute(k_zmat, cudaFuncAttributeMaxDynamicSharedMemorySize, SM_ZMAT);
    cudaFuncSetAttribute(k_gmat, cudaFuncAttributeMaxDynamicSharedMemorySize, SM_GMAT);
    cudaFuncSetAttribute(k_out,  cudaFuncAttributeMaxDynamicSharedMemorySize, SM_OUT);

    k_pmat<<<dim3(4, 4, BSZ * 2), 256, SM_PMAT>>>(q, k);
    k_umat<<<dim3(4, NH, BSZ),    256, SM_UMAT>>>(Wk);
    k_attn<<<BSZ * NH,            256>>>(Wq);
    k_zmat<<<dim3(4, BSZ * NH),   256, SM_ZMAT>>>(Wo);
    k_gmat<<<dim3(8, 4, BSZ),     256, SM_GMAT>>>(Wv);
    k_out <<<dim3(4, 32, BSZ),    256, SM_OUT>>>(v, out);
}

// round 10
// speedup vs baseline: 1.0822x; 1.0118x over previous
#include <cuda_runtime.h>
#include <cstdint>
#include <math.h>

// Problem constants
#define BSZ  8
#define CDIM 4096
#define TDIM 512
#define NH   8
#define HDIM 64
#define ODIM 512
#define SCALE_INV (1.0f / 22.62741699796952f)   // 1/sqrt(512)

// ---------------- scratch (static device globals; allocation-free) ----------
// g_Pd[b][t][1024]: cols 0-511 = K-half-0 partial of P, 512-1023 = half-1.
// (tf32-pre-rounded)  U = (P0+P1)@Wk^T == [P0|P1] @ [Wk|Wk]^T over K=1024.
__device__ __align__(256) float g_Pd[BSZ * TDIM * 1024];
__device__ __align__(256) float g_U [BSZ * NH * TDIM * HDIM];
__device__ __align__(256) float g_W [BSZ * NH * HDIM * HDIM];  // W^T, tf32-pre-rounded
__device__ __align__(256) float g_Z [BSZ * TDIM * TDIM];       // tf32-pre-rounded
__device__ __align__(256) float g_G [BSZ * TDIM * TDIM];       // tf32-pre-rounded

// ---------------- helpers ----------------
__device__ __forceinline__ unsigned f2tf32(float x) {
    unsigned r;
    asm("cvt.rna.tf32.f32 %0, %1;" : "=r"(r) : "f"(x));
    return r;
}

template<bool PRE>
__device__ __forceinline__ unsigned frag_bits(float x) {
    return PRE ? __float_as_uint(x) : f2tf32(x);
}

__device__ __forceinline__ uint32_t smem_u32(const void* p) {
    uint32_t a;
    asm("{ .reg .u64 t; cvta.to.shared.u64 t, %1; cvt.u32.u64 %0, t; }" : "=r"(a) : "l"(p));
    return a;
}

__device__ __forceinline__ void cp16(uint32_t dst, const float* src) {
    asm volatile("cp.async.cg.shared.global [%0], [%1], 16;" :: "r"(dst), "l"(src));
}
#define CP_COMMIT() asm volatile("cp.async.commit_group;" ::: "memory")
#define CP_WAIT1()  asm volatile("cp.async.wait_group 1;"  ::: "memory")

__device__ __forceinline__ void mma_tf32(float* c, const unsigned* a, const unsigned* b) {
    asm("mma.sync.aligned.m16n8k8.row.col.f32.tf32.tf32.f32 "
        "{%0,%1,%2,%3},{%4,%5,%6,%7},{%8,%9},{%0,%1,%2,%3};"
        : "+f"(c[0]), "+f"(c[1]), "+f"(c[2]), "+f"(c[3])
        : "r"(a[0]), "r"(a[1]), "r"(a[2]), "r"(a[3]),
          "r"(b[0]), "r"(b[1]));
}

// =============================================================================
// BIG engine (k_pmat / k_out): 128x128 CTA tile, 128 threads = 4 warps (2Mx2N),
// warp tile 64x64 (max register reuse -> fragment-LDS traffic halved), BK=32,
// 3-stage cp.async, conflict-free pitches (K-contig 36, scatter 136), occ 2.
// =============================================================================
template<bool AKC, bool BKC, bool APRE, bool BPRE, bool DPRE>
__device__ __forceinline__ void gemm_big(const float* __restrict__ A, int lda,
                                         const float* __restrict__ B, int ldb,
                                         int NC, float* __restrict__ D, int ldd)
{
    extern __shared__ float sm[];
    constexpr int ASTAGE = AKC ? 128 * 36 : 32 * 136;
    constexpr int BSTAGE = BKC ? 128 * 36 : 32 * 136;
    constexpr int STAGE  = ASTAGE + BSTAGE;

    const int tid  = threadIdx.x;
    const int lane = tid & 31;
    const int w    = tid >> 5;
    const int g    = lane >> 2;
    const int qd   = lane & 3;
    const int mb   = (w & 1) * 64;
    const int nb   = (w >> 1) * 64;

    auto issue = [&](int c) {
        float* stA = sm + (c % 3) * STAGE;
        if (AKC) {
#pragma unroll
            for (int it = 0; it < 8; it++) {
                int i   = tid + it * 128;
                int row = i >> 3, kc = (i & 7) * 4;
                cp16(smem_u32(stA + row * 36 + kc),
                     A + (size_t)row * lda + (size_t)c * 32 + kc);
            }
        } else {
#pragma unroll
            for (int it = 0; it < 8; it++) {
                int i  = tid + it * 128;
                int kr = i >> 5, mc = (i & 31) * 4;
                cp16(smem_u32(stA + kr * 136 + mc),
                     A + (size_t)(c * 32 + kr) * lda + mc);
            }
        }
        float* stB = stA + ASTAGE;
        if (BKC) {
#pragma unroll
            for (int it = 0; it < 8; it++) {
                int i   = tid + it * 128;
                int row = i >> 3, kc = (i & 7) * 4;
                cp16(smem_u32(stB + row * 36 + kc),
                     B + (size_t)row * ldb + (size_t)c * 32 + kc);
            }
        } else {
#pragma unroll
            for (int it = 0; it < 8; it++) {
                int i  = tid + it * 128;
                int kr = i >> 5, nc = (i & 31) * 4;
                cp16(smem_u32(stB + kr * 136 + nc),
                     B + (size_t)(c * 32 + kr) * ldb + nc);
            }
        }
    };

    float acc[4][8][4];
#pragma unroll
    for (int mi = 0; mi < 4; mi++)
#pragma unroll
        for (int ni = 0; ni < 8; ni++)
#pragma unroll
            for (int r = 0; r < 4; r++) acc[mi][ni][r] = 0.f;

    issue(0); CP_COMMIT();
    issue(1); CP_COMMIT();

    for (int c = 0; c < NC; c++) {
        CP_WAIT1();
        __syncthreads();
        const float* As = sm + (c % 3) * STAGE;
        const float* Bs = As + ASTAGE;

#pragma unroll
        for (int ks = 0; ks < 4; ks++) {
            const int kk = ks * 8;
            unsigned af[4][4], bf[8][2];
#pragma unroll
            for (int mi = 0; mi < 4; mi++) {
                const int m = mb + mi * 16 + g;
                if (AKC) {
                    const float* p = As + m * 36 + kk + qd;
                    af[mi][0] = frag_bits<APRE>(p[0]);
                    af[mi][1] = frag_bits<APRE>(p[8 * 36]);
                    af[mi][2] = frag_bits<APRE>(p[4]);
                    af[mi][3] = frag_bits<APRE>(p[8 * 36 + 4]);
                } else {
                    const float* p = As + (kk + qd) * 136 + m;
                    af[mi][0] = frag_bits<APRE>(p[0]);
                    af[mi][1] = frag_bits<APRE>(p[8]);
                    af[mi][2] = frag_bits<APRE>(p[4 * 136]);
                    af[mi][3] = frag_bits<APRE>(p[4 * 136 + 8]);
                }
            }
#pragma unroll
            for (int ni = 0; ni < 8; ni++) {
                const int n = nb + ni * 8 + g;
                if (BKC) {
                    const float* p = Bs + n * 36 + kk + qd;
                    bf[ni][0] = frag_bits<BPRE>(p[0]);
                    bf[ni][1] = frag_bits<BPRE>(p[4]);
                } else {
                    const float* p = Bs + (kk + qd) * 136 + n;
                    bf[ni][0] = frag_bits<BPRE>(p[0]);
                    bf[ni][1] = frag_bits<BPRE>(p[4 * 136]);
                }
            }
#pragma unroll
            for (int mi = 0; mi < 4; mi++)
#pragma unroll
                for (int ni = 0; ni < 8; ni++)
                    mma_tf32(acc[mi][ni], af[mi], bf[ni]);
        }

        if (c + 2 < NC) issue(c + 2);
        CP_COMMIT();
    }

#pragma unroll
    for (int mi = 0; mi < 4; mi++)
#pragma unroll
        for (int ni = 0; ni < 8; ni++) {
            const int row = mb + mi * 16 + g;
            const int col = nb + ni * 8 + 2 * qd;
            float v0 = acc[mi][ni][0], v1 = acc[mi][ni][1];
            float v2 = acc[mi][ni][2], v3 = acc[mi][ni][3];
            if (DPRE) {
                v0 = __uint_as_float(f2tf32(v0)); v1 = __uint_as_float(f2tf32(v1));
                v2 = __uint_as_float(f2tf32(v2)); v3 = __uint_as_float(f2tf32(v3));
            }
            *(float2*)&D[(size_t)row * ldd + col]       = make_float2(v0, v1);
            *(float2*)&D[(size_t)(row + 8) * ldd + col] = make_float2(v2, v3);
        }
}

// =============================================================================
// 128x64 engine: BK=32, 256 thr (8 warps = 4M x 2N, warp tile 32x32), 2-stage
// cp.async, both fragment operands double-buffered, occ 3.  (k_umat / k_gmat.)
// =============================================================================
template<bool AKC, bool BKC, bool APRE, bool BPRE, bool DPRE>
__device__ __forceinline__ void gemm_db(const float* __restrict__ A, int lda,
                                        const float* __restrict__ B, int ldb,
                                        unsigned kmaskB,
                                        int NC, float* __restrict__ D, int ldd)
{
    extern __shared__ float sm[];
    constexpr int ASTAGE = AKC ? 128 * 36 : 32 * 136;
    constexpr int BSTAGE = BKC ? 64 * 36 : 32 * 72;
    constexpr int STAGE  = ASTAGE + BSTAGE;

    const int tid  = threadIdx.x;
    const int lane = tid & 31;
    const int w    = tid >> 5;
    const int g    = lane >> 2;
    const int qd   = lane & 3;
    const int mb   = (w & 3) * 32;
    const int nb   = (w >> 2) * 32;

    auto issue = [&](int c) {
        float* stA = sm + (c & 1) * STAGE;
        if (AKC) {
#pragma unroll
            for (int it = 0; it < 4; it++) {
                int i   = tid + it * 256;
                int row = i >> 3, kc = (i & 7) * 4;
                cp16(smem_u32(stA + row * 36 + kc),
                     A + (size_t)row * lda + (size_t)c * 32 + kc);
            }
        } else {
#pragma unroll
            for (int it = 0; it < 4; it++) {
                int i  = tid + it * 256;
                int kr = i >> 5, mc = (i & 31) * 4;
                cp16(smem_u32(stA + kr * 136 + mc),
                     A + (size_t)(c * 32 + kr) * lda + mc);
            }
        }
        float* stB = stA + ASTAGE;
        unsigned koff = ((unsigned)c * 32u) & kmaskB;
        if (BKC) {
#pragma unroll
            for (int it = 0; it < 2; it++) {
                int i   = tid + it * 256;
                int row = i >> 3, kc = (i & 7) * 4;
                cp16(smem_u32(stB + row * 36 + kc),
                     B + (size_t)row * ldb + koff + kc);
            }
        } else {
#pragma unroll
            for (int it = 0; it < 2; it++) {
                int i  = tid + it * 256;
                int kr = i >> 4, nc = (i & 15) * 4;
                cp16(smem_u32(stB + kr * 72 + nc),
                     B + (size_t)(koff + kr) * ldb + nc);
            }
        }
    };

    auto loadA = [&](const float* As, int ks, unsigned af[2][4]) {
        const int kk = ks * 8;
#pragma unroll
        for (int mi = 0; mi < 2; mi++) {
            const int m = mb + mi * 16 + g;
            if (AKC) {
                const float* p = As + m * 36 + kk + qd;
                af[mi][0] = frag_bits<APRE>(p[0]);
                af[mi][1] = frag_bits<APRE>(p[8 * 36]);
                af[mi][2] = frag_bits<APRE>(p[4]);
                af[mi][3] = frag_bits<APRE>(p[8 * 36 + 4]);
            } else {
                const float* p = As + (kk + qd) * 136 + m;
                af[mi][0] = frag_bits<APRE>(p[0]);
                af[mi][1] = frag_bits<APRE>(p[8]);
                af[mi][2] = frag_bits<APRE>(p[4 * 136]);
                af[mi][3] = frag_bits<APRE>(p[4 * 136 + 8]);
            }
        }
    };

    auto loadB = [&](const float* Bs, int ks, unsigned bf[4][2]) {
        const int kk = ks * 8;
#pragma unroll
        for (int ni = 0; ni < 4; ni++) {
            const int n = nb + ni * 8 + g;
            if (BKC) {
                const float* p = Bs + n * 36 + kk + qd;
                bf[ni][0] = frag_bits<BPRE>(p[0]);
                bf[ni][1] = frag_bits<BPRE>(p[4]);
            } else {
                const float* p = Bs + (kk + qd) * 72 + n;
                bf[ni][0] = frag_bits<BPRE>(p[0]);
                bf[ni][1] = frag_bits<BPRE>(p[4 * 72]);
            }
        }
    };

    float acc[2][4][4];
#pragma unroll
    for (int mi = 0; mi < 2; mi++)
#pragma unroll
        for (int ni = 0; ni < 4; ni++)
#pragma unroll
            for (int r = 0; r < 4; r++) acc[mi][ni][r] = 0.f;

    issue(0); CP_COMMIT();
    issue(1); CP_COMMIT();

    for (int c = 0; c < NC; c++) {
        CP_WAIT1();
        __syncthreads();
        const float* As = sm + (c & 1) * STAGE;
        const float* Bs = As + ASTAGE;

        unsigned afd[2][2][4], bfd[2][4][2];
        loadA(As, 0, afd[0]);
        loadB(Bs, 0, bfd[0]);
#pragma unroll
        for (int ks = 0; ks < 4; ks++) {
            const int cur = ks & 1;
            if (ks < 3) {
                loadA(As, ks + 1, afd[cur ^ 1]);
                loadB(Bs, ks + 1, bfd[cur ^ 1]);
            }
#pragma unroll
            for (int mi = 0; mi < 2; mi++)
#pragma unroll
                for (int ni = 0; ni < 4; ni++)
                    mma_tf32(acc[mi][ni], afd[cur][mi], bfd[cur][ni]);
        }

        __syncthreads();
        if (c + 2 < NC) issue(c + 2);
        CP_COMMIT();
    }

#pragma unroll
    for (int mi = 0; mi < 2; mi++)
#pragma unroll
        for (int ni = 0; ni < 4; ni++) {
            const int row = mb + mi * 16 + g;
            const int col = nb + ni * 8 + 2 * qd;
            float v0 = acc[mi][ni][0], v1 = acc[mi][ni][1];
            float v2 = acc[mi][ni][2], v3 = acc[mi][ni][3];
            if (DPRE) {
                v0 = __uint_as_float(f2tf32(v0)); v1 = __uint_as_float(f2tf32(v1));
                v2 = __uint_as_float(f2tf32(v2)); v3 = __uint_as_float(f2tf32(v3));
            }
            *(float2*)&D[(size_t)row * ldd + col]       = make_float2(v0, v1);
            *(float2*)&D[(size_t)(row + 8) * ldd + col] = make_float2(v2, v3);
        }
}

// =============================================================================
// 128 x NCOLS engine (k_zmat): 256 thr, 3-stage, occ 2.
// =============================================================================
template<int NCOLS, bool AKC, bool BKC, bool APRE, bool BPRE, bool DPRE>
__device__ __forceinline__ void gemm_cp(const float* __restrict__ A, int lda,
                                        const float* __restrict__ B, int ldb,
                                        unsigned kmaskB,
                                        int NC, float* __restrict__ D, int ldd)
{
    extern __shared__ float sm[];
    constexpr int BPITCH = NCOLS + 8;
    constexpr int ASTAGE = AKC ? 128 * 36 : 32 * 136;
    constexpr int BSTAGE = BKC ? NCOLS * 36 : 32 * BPITCH;
    constexpr int STAGE  = ASTAGE + BSTAGE;
    constexpr int NI     = (NCOLS / 2) / 8;

    const int tid  = threadIdx.x;
    const int lane = tid & 31;
    const int w    = tid >> 5;
    const int g    = lane >> 2;
    const int qd   = lane & 3;
    const int mb   = (w >> 1) * 32;
    const int nb   = (w & 1) * (NCOLS / 2);

    auto issue = [&](int c) {
        float* stA = sm + (c % 3) * STAGE;
        if (AKC) {
#pragma unroll
            for (int it = 0; it < 4; it++) {
                int i   = tid + it * 256;
                int row = i >> 3, kc = (i & 7) * 4;
                cp16(smem_u32(stA + row * 36 + kc),
                     A + (size_t)row * lda + (size_t)c * 32 + kc);
            }
        } else {
#pragma unroll
            for (int it = 0; it < 4; it++) {
                int i  = tid + it * 256;
                int kr = i >> 5, mc = (i & 31) * 4;
                cp16(smem_u32(stA + kr * 136 + mc),
                     A + (size_t)(c * 32 + kr) * lda + mc);
            }
        }
        float* stB = stA + ASTAGE;
        unsigned koff = ((unsigned)c * 32u) & kmaskB;
        if (BKC) {
#pragma unroll
            for (int it = 0; it < NCOLS / 32; it++) {
                int i   = tid + it * 256;
                int row = i >> 3, kc = (i & 7) * 4;
                cp16(smem_u32(stB + row * 36 + kc),
                     B + (size_t)row * ldb + koff + kc);
            }
        } else {
#pragma unroll
            for (int it = 0; it < NCOLS / 32; it++) {
                int i  = tid + it * 256;
                int kr = i / (NCOLS / 4);
                int nc = (i % (NCOLS / 4)) * 4;
                cp16(smem_u32(stB + (size_t)kr * BPITCH + nc),
                     B + (size_t)(koff + kr) * ldb + nc);
            }
        }
    };

    auto loadA = [&](const float* As, int ks, unsigned af[2][4]) {
        const int kk = ks * 8;
#pragma unroll
        for (int mi = 0; mi < 2; mi++) {
            const int m = mb + mi * 16 + g;
            if (AKC) {
                const float* p = As + m * 36 + kk + qd;
                af[mi][0] = frag_bits<APRE>(p[0]);
                af[mi][1] = frag_bits<APRE>(p[8 * 36]);
                af[mi][2] = frag_bits<APRE>(p[4]);
                af[mi][3] = frag_bits<APRE>(p[8 * 36 + 4]);
            } else {
                const float* p = As + (kk + qd) * 136 + m;
                af[mi][0] = frag_bits<APRE>(p[0]);
                af[mi][1] = frag_bits<APRE>(p[8]);
                af[mi][2] = frag_bits<APRE>(p[4 * 136]);
                af[mi][3] = frag_bits<APRE>(p[4 * 136 + 8]);
            }
        }
    };

    float acc[2][NI][4];
#pragma unroll
    for (int mi = 0; mi < 2; mi++)
#pragma unroll
        for (int ni = 0; ni < NI; ni++)
#pragma unroll
            for (int r = 0; r < 4; r++) acc[mi][ni][r] = 0.f;

    issue(0); CP_COMMIT();
    issue(1); CP_COMMIT();

    for (int c = 0; c < NC; c++) {
        CP_WAIT1();
        __syncthreads();
        const float* As = sm + (c % 3) * STAGE;
        const float* Bs = As + ASTAGE;

        unsigned afd[2][2][4];
        loadA(As, 0, afd[0]);
#pragma unroll
        for (int ks = 0; ks < 4; ks++) {
            const int cur = ks & 1;
            if (ks < 3) loadA(As, ks + 1, afd[cur ^ 1]);
            const int kk = ks * 8;
            unsigned bf[NI][2];
#pragma unroll
            for (int ni = 0; ni < NI; ni++) {
                const int n = nb + ni * 8 + g;
                if (BKC) {
                    const float* p = Bs + n * 36 + kk + qd;
                    bf[ni][0] = frag_bits<BPRE>(p[0]);
                    bf[ni][1] = frag_bits<BPRE>(p[4]);
                } else {
                    const float* p = Bs + (kk + qd) * BPITCH + n;
                    bf[ni][0] = frag_bits<BPRE>(p[0]);
                    bf[ni][1] = frag_bits<BPRE>(p[4 * BPITCH]);
                }
            }
#pragma unroll
            for (int mi = 0; mi < 2; mi++)
#pragma unroll
                for (int ni = 0; ni < NI; ni++)
                    mma_tf32(acc[mi][ni], afd[cur][mi], bf[ni]);
        }

        if (c + 2 < NC) issue(c + 2);
        CP_COMMIT();
    }

#pragma unroll
    for (int mi = 0; mi < 2; mi++)
#pragma unroll
        for (int ni = 0; ni < NI; ni++) {
            const int row = mb + mi * 16 + g;
            const int col = nb + ni * 8 + 2 * qd;
            float v0 = acc[mi][ni][0], v1 = acc[mi][ni][1];
            float v2 = acc[mi][ni][2], v3 = acc[mi][ni][3];
            if (DPRE) {
                v0 = __uint_as_float(f2tf32(v0)); v1 = __uint_as_float(f2tf32(v1));
                v2 = __uint_as_float(f2tf32(v2)); v3 = __uint_as_float(f2tf32(v3));
            }
            *(float2*)&D[(size_t)row * ldd + col]       = make_float2(v0, v1);
            *(float2*)&D[(size_t)(row + 8) * ldd + col] = make_float2(v2, v3);
        }
}

// =============================================================================
// K1: P half: g_Pd[b][t][ph*512+s] = sum_{c in half ph} q[b][c][t] k[b][c][s]
// BIG engine, split-K=2 -> grid 4x4x16 = 256 CTAs of 128 thr, occ 2.
// =============================================================================
__global__ void __launch_bounds__(128, 2) k_pmat(const float* __restrict__ q,
                                                 const float* __restrict__ kk_)
{
    const int z  = blockIdx.z;
    const int b  = z >> 1;
    const int ph = z & 1;
    const int t0 = blockIdx.y * 128;
    const int s0 = blockIdx.x * 128;
    const float* Ab = q   + (size_t)b * CDIM * TDIM + (size_t)ph * (CDIM / 2) * TDIM + t0;
    const float* Bb = kk_ + (size_t)b * CDIM * TDIM + (size_t)ph * (CDIM / 2) * TDIM + s0;
    float* D = g_Pd + (size_t)b * TDIM * 1024 + (size_t)t0 * 1024 + ph * 512 + s0;
    gemm_big<false, false, false, false, true>(
        Ab, TDIM, Bb, TDIM, (CDIM / 2) / 32, D, 1024);
}

// =============================================================================
// K2a: U[b,h][t][e] = sum_{k'=0..1023} g_Pd[b][t][k'] * Wk[h][e][k' mod 512]
// =============================================================================
__global__ void __launch_bounds__(256, 3) k_umat(const float* __restrict__ Wk)
{
    const int b  = blockIdx.z;
    const int h  = blockIdx.y;
    const int t0 = blockIdx.x * 128;
    const float* Ab = g_Pd + (size_t)b * TDIM * 1024 + (size_t)t0 * 1024;
    const float* Bb = Wk + (size_t)h * HDIM * TDIM;
    float* D = g_U + (size_t)(b * NH + h) * TDIM * HDIM + (size_t)t0 * HDIM;
    gemm_db<true, true, true, false, false>(
        Ab, 1024, Bb, TDIM, 511u, 1024 / 32, D, HDIM);
}

// =============================================================================
// K2b: per (b,h): S = Wq_h @ U / sqrt(512); W = softmax_rows(S);
// store W^T (tf32-pre-rounded) -> g_W[bh][e][d]
// =============================================================================
__global__ void __launch_bounds__(256) k_attn(const float* __restrict__ Wq)
{
    const int bh = blockIdx.x;
    const int h = bh & 7;

    __shared__ float Ws[64][65];
    __shared__ float Us[32][68];
    __shared__ float Wqs[64][33];

    const float* Ub  = g_U + (size_t)bh * TDIM * HDIM;
    const float* Wqh = Wq + (size_t)h * HDIM * TDIM;

    const int tid = threadIdx.x;
    const int tx = tid & 15, ty = tid >> 4;

    float acc[4][4];
#pragma unroll
    for (int m = 0; m < 4; m++)
#pragma unroll
        for (int n = 0; n < 4; n++) acc[m][n] = 0.f;

    for (int t0 = 0; t0 < TDIM; t0 += 32) {
#pragma unroll
        for (int i = 0; i < 2; i++) {
            int idx = tid + i * 256;
            int tl  = idx >> 4;
            int eq  = (idx & 15) * 4;
            *(float4*)&Us[tl][eq] = *(const float4*)&Ub[(size_t)(t0 + tl) * HDIM + eq];
        }
#pragma unroll
        for (int i = 0; i < 2; i++) {
            int idx = tid + i * 256;
            int d   = idx >> 3;
            int tq  = (idx & 7) * 4;
            float4 a = *(const float4*)&Wqh[(size_t)d * TDIM + t0 + tq];
            Wqs[d][tq + 0] = a.x; Wqs[d][tq + 1] = a.y;
            Wqs[d][tq + 2] = a.z; Wqs[d][tq + 3] = a.w;
        }
        __syncthreads();
#pragma unroll
        for (int tl = 0; tl < 32; tl++) {
            float ra[4], rb[4];
#pragma unroll
            for (int m = 0; m < 4; m++) ra[m] = Wqs[ty * 4 + m][tl];
#pragma unroll
            for (int n = 0; n < 4; n++) rb[n] = Us[tl][tx * 4 + n];
#pragma unroll
            for (int m = 0; m < 4; m++)
#pragma unroll
                for (int n = 0; n < 4; n++) acc[m][n] += ra[m] * rb[n];
        }
        __syncthreads();
    }

#pragma unroll
    for (int m = 0; m < 4; m++)
#pragma unroll
        for (int n = 0; n < 4; n++)
            Ws[ty * 4 + m][tx * 4 + n] = acc[m][n] * SCALE_INV;
    __syncthreads();

    if (tid < 64) {
        float mx = -1e30f;
#pragma unroll 8
        for (int e = 0; e < 64; e++) mx = fmaxf(mx, Ws[tid][e]);
        float sum = 0.f;
#pragma unroll 8
        for (int e = 0; e < 64; e++) { float ex = expf(Ws[tid][e] - mx); Ws[tid][e] = ex; sum += ex; }
        float inv = 1.f / sum;
#pragma unroll 8
        for (int e = 0; e < 64; e++) Ws[tid][e] *= inv;
    }
    __syncthreads();

    float* Wt = g_W + (size_t)bh * HDIM * HDIM;
    for (int idx = tid; idx < HDIM * HDIM; idx += 256) {
        int e = idx >> 6, d = idx & 63;
        Wt[(size_t)e * HDIM + d] = __uint_as_float(f2tf32(Ws[d][e]));
    }
}

// =============================================================================
// K2c: Z[b][o][h*64+e] = sum_d Wo[o][h*64+d] * W_h[d][e]
// =============================================================================
__global__ void __launch_bounds__(256, 2) k_zmat(const float* __restrict__ Wo)
{
    const int bh = blockIdx.y;
    const int b = bh >> 3, h = bh & 7;
    const int o0 = blockIdx.x * 128;
    const float* Ab = Wo + (size_t)o0 * (NH * HDIM) + h * HDIM;
    const float* Bb = g_W + (size_t)bh * HDIM * HDIM;
    float* D = g_Z + (size_t)b * TDIM * TDIM + (size_t)o0 * TDIM + h * HDIM;
    gemm_cp<64, true, true, false, true, true>(
        Ab, NH * HDIM, Bb, HDIM, 0x7fffffffu, HDIM / 32, D, TDIM);
}

// =============================================================================
// K3: G[b][o][t] = sum_j Z[b][o][j] * Wv_flat[j][t]
// =============================================================================
__global__ void __launch_bounds__(256, 3) k_gmat(const float* __restrict__ Wv)
{
    const int b  = blockIdx.z;
    const int o0 = blockIdx.y * 128;
    const int t0 = blockIdx.x * 64;
    const float* Ab = g_Z + (size_t)b * TDIM * TDIM + (size_t)o0 * TDIM;
    const float* Bb = Wv + t0;
    float* D = g_G + (size_t)b * TDIM * TDIM + (size_t)o0 * TDIM + t0;
    gemm_db<true, false, true, false, true>(
        Ab, TDIM, Bb, TDIM, 0x7fffffffu, TDIM / 32, D, TDIM);
}

// =============================================================================
// K4: out[b][c][o] = sum_t v[b][c][t] * G[b][o][t]
// BIG engine, grid 4x32x8 = 1024 CTAs of 128 thr, occ 2.
// =============================================================================
__global__ void __launch_bounds__(128, 2) k_out(const float* __restrict__ v,
                                                float* __restrict__ out)
{
    const int b  = blockIdx.z;
    const int c0 = blockIdx.y * 128;
    const int o0 = blockIdx.x * 128;
    const float* Ab = v + (size_t)b * CDIM * TDIM + (size_t)c0 * TDIM;
    const float* Bb = g_G + (size_t)b * TDIM * TDIM + (size_t)o0 * TDIM;
    float* D = out + (size_t)b * CDIM * ODIM + (size_t)c0 * ODIM + o0;
    gemm_big<true, true, false, true, false>(
        Ab, TDIM, Bb, TDIM, TDIM / 32, D, ODIM);
}

// =============================================================================
extern "C" void kernel_launch(void* const* d_in, const int* in_sizes, int n_in,
                              void* d_out, int out_size)
{
    const float* q  = (const float*)d_in[0];
    const float* k  = (const float*)d_in[1];
    const float* v  = (const float*)d_in[2];
    const float* Wq = (const float*)d_in[3];
    const float* Wk = (const float*)d_in[4];
    const float* Wv = (const float*)d_in[5];
    const float* Wo = (const float*)d_in[6];
    float* out = (float*)d_out;
    (void)in_sizes; (void)n_in; (void)out_size;

    const int SM_PMAT = 3 * (32 * 136 + 32 * 136) * 4;    // 104448
    const int SM_UMAT = 2 * (128 * 36 + 64 * 36) * 4;     //  55296
    const int SM_GMAT = 2 * (128 * 36 + 32 * 72) * 4;     //  55296
    const int SM_ZMAT = 3 * (128 * 36 + 64 * 36) * 4;     //  82944
    const int SM_OUT  = 3 * (128 * 36 + 128 * 36) * 4;    // 110592

    cudaFuncSetAttribute(k_pmat, cudaFuncAttributeMaxDynamicSharedMemorySize, SM_PMAT);
    cudaFuncSetAttribute(k_umat, cudaFuncAttributeMaxDynamicSharedMemorySize, SM_UMAT);
    cudaFuncSetAttribute(k_zmat, cudaFuncAttributeMaxDynamicSharedMemorySize, SM_ZMAT);
    cudaFuncSetAttribute(k_gmat, cudaFuncAttributeMaxDynamicSharedMemorySize, SM_GMAT);
    cudaFuncSetAttribute(k_out,  cudaFuncAttributeMaxDynamicSharedMemorySize, SM_OUT);

    k_pmat<<<dim3(4, 4, BSZ * 2), 128, SM_PMAT>>>(q, k);
    k_umat<<<dim3(4, NH, BSZ),    256, SM_UMAT>>>(Wk);
    k_attn<<<BSZ * NH,            256>>>(Wq);
    k_zmat<<<dim3(4, BSZ * NH),   256, SM_ZMAT>>>(Wo);
    k_gmat<<<dim3(8, 4, BSZ),     256, SM_GMAT>>>(Wv);
    k_out <<<dim3(4, 32, BSZ),    128, SM_OUT>>>(v, out);
}

// round 11
// speedup vs baseline: 1.2848x; 1.1873x over previous
#include <cuda_runtime.h>
#include <cuda_fp16.h>
#include <cstdint>
#include <math.h>

// Problem constants
#define BSZ  8
#define CDIM 4096
#define TDIM 512
#define NH   8
#define HDIM 64
#define ODIM 512
#define SCALE_INV (1.0f / 22.62741699796952f)   // 1/sqrt(512)

// ---------------- scratch (static device globals; allocation-free) ----------
// fp16 staging of inputs (K-contiguous layouts for every GEMM):
__device__ __align__(256) __half g_qT [BSZ * TDIM * CDIM];   // qT[b][t][c]
__device__ __align__(256) __half g_kT [BSZ * TDIM * CDIM];   // kT[b][s][c]
__device__ __align__(256) __half g_vh [BSZ * CDIM * TDIM];   // v fp16 in-layout
__device__ __align__(256) __half g_Wkh[NH * HDIM * TDIM];    // Wk fp16
__device__ __align__(256) __half g_Woh[ODIM * NH * HDIM];    // Wo fp16
__device__ __align__(256) __half g_WvT[TDIM * TDIM];         // WvT[t][j]
// pipeline scratch:
// g_Pd[b][t][1024]: cols 0-511 = K-half-0 partial of P, 512-1023 = half-1.
__device__ __align__(256) __half g_Pd [BSZ * TDIM * 1024];
__device__ __align__(256) float  g_U  [BSZ * NH * TDIM * HDIM];
__device__ __align__(256) __half g_W  [BSZ * NH * HDIM * HDIM]; // W^T[e][d]
__device__ __align__(256) __half g_Z  [BSZ * TDIM * TDIM];
__device__ __align__(256) __half g_G  [BSZ * TDIM * TDIM];

// ---------------- helpers ----------------
__device__ __forceinline__ uint32_t smem_u32(const void* p) {
    uint32_t a;
    asm("{ .reg .u64 t; cvta.to.shared.u64 t, %1; cvt.u32.u64 %0, t; }" : "=r"(a) : "l"(p));
    return a;
}

__device__ __forceinline__ void cp16(uint32_t dst, const void* src) {
    asm volatile("cp.async.cg.shared.global [%0], [%1], 16;" :: "r"(dst), "l"(src));
}
#define CP_COMMIT() asm volatile("cp.async.commit_group;" ::: "memory")
#define CP_WAIT1()  asm volatile("cp.async.wait_group 1;"  ::: "memory")

__device__ __forceinline__ void mma_f16(float* c, const unsigned* a, const unsigned* b) {
    asm("mma.sync.aligned.m16n8k16.row.col.f32.f16.f16.f32 "
        "{%0,%1,%2,%3},{%4,%5,%6,%7},{%8,%9},{%0,%1,%2,%3};"
        : "+f"(c[0]), "+f"(c[1]), "+f"(c[2]), "+f"(c[3])
        : "r"(a[0]), "r"(a[1]), "r"(a[2]), "r"(a[3]),
          "r"(b[0]), "r"(b[1]));
}

// XOR-swizzled smem layout: rows of 32 halves (zero pad), 8-half chunks
// permuted by chunk ^ ((row>>1)&3).  Verified conflict-free for both the
// 16B cp.async stores and the 32-bit fragment loads.
__device__ __forceinline__ int hoff(int row, int chunk) {
    return row * 32 + ((chunk ^ ((row >> 1) & 3)) << 3);
}

// =============================================================================
// Unified fp16 GEMM engine: 128(M) x NCOLS(N) CTA tile, BK=32 (2 k16-steps),
// 256 thr (8 warps; 128: 4Mx2N warp 32x64; 64: 4Mx2N warp 32x32),
// 3-stage cp.async, all operands K-contiguous fp16 in gmem.
// DHALF: D stored fp16 (else fp32).  kmaskB: wrap mask on B's K offset.
// =============================================================================
template<int NCOLS, bool DHALF>
__device__ __forceinline__ void gemm_h(const __half* __restrict__ A, int lda,
                                       const __half* __restrict__ B, int ldb,
                                       unsigned kmaskB, int NC,
                                       void* __restrict__ Dv, int ldd)
{
    extern __shared__ __half smh[];
    constexpr int ASTAGE = 128 * 32;          // halves
    constexpr int BSTAGE = NCOLS * 32;
    constexpr int STAGE  = ASTAGE + BSTAGE;
    constexpr int NI     = (NCOLS == 128) ? 8 : 4;

    const int tid  = threadIdx.x;
    const int lane = tid & 31;
    const int w    = tid >> 5;
    const int g    = lane >> 2;
    const int qd   = lane & 3;
    const int mb   = (NCOLS == 128) ? (w >> 1) * 32 : (w & 3) * 32;
    const int nb   = (NCOLS == 128) ? (w & 1) * 64 : (w >> 2) * 32;

    auto issue = [&](int c) {
        __half* stA = smh + (c % 3) * STAGE;
        // A: 128 rows x 32 halves = 512 16B-chunks
#pragma unroll
        for (int it = 0; it < 2; it++) {
            int i = tid + it * 256;
            int row = i >> 2, kc = i & 3;
            cp16(smem_u32(stA + hoff(row, kc)),
                 A + (size_t)row * lda + (size_t)c * 32 + kc * 8);
        }
        __half* stB = stA + ASTAGE;
        unsigned koff = ((unsigned)c * 32u) & kmaskB;
#pragma unroll
        for (int it = 0; it < NCOLS / 64; it++) {
            int i = tid + it * 256;
            int row = i >> 2, kc = i & 3;
            cp16(smem_u32(stB + hoff(row, kc)),
                 B + (size_t)row * ldb + koff + kc * 8);
        }
    };

    float acc[2][NI][4];
#pragma unroll
    for (int mi = 0; mi < 2; mi++)
#pragma unroll
        for (int ni = 0; ni < NI; ni++)
#pragma unroll
            for (int r = 0; r < 4; r++) acc[mi][ni][r] = 0.f;

    issue(0); CP_COMMIT();
    issue(1); CP_COMMIT();

    for (int c = 0; c < NC; c++) {
        CP_WAIT1();
        __syncthreads();
        const unsigned* As = (const unsigned*)(smh + (c % 3) * STAGE);
        const unsigned* Bs = As + ASTAGE / 2;

#pragma unroll
        for (int ks = 0; ks < 2; ks++) {
            unsigned af[2][4], bf[NI][2];
#pragma unroll
            for (int mi = 0; mi < 2; mi++) {
                const int m = mb + mi * 16 + g;
                af[mi][0] = As[hoff(m,     ks * 2)     / 2 + qd];
                af[mi][1] = As[hoff(m + 8, ks * 2)     / 2 + qd];
                af[mi][2] = As[hoff(m,     ks * 2 + 1) / 2 + qd];
                af[mi][3] = As[hoff(m + 8, ks * 2 + 1) / 2 + qd];
            }
#pragma unroll
            for (int ni = 0; ni < NI; ni++) {
                const int n = nb + ni * 8 + g;
                bf[ni][0] = Bs[hoff(n, ks * 2)     / 2 + qd];
                bf[ni][1] = Bs[hoff(n, ks * 2 + 1) / 2 + qd];
            }
#pragma unroll
            for (int mi = 0; mi < 2; mi++)
#pragma unroll
                for (int ni = 0; ni < NI; ni++)
                    mma_f16(acc[mi][ni], af[mi], bf[ni]);
        }

        if (c + 2 < NC) issue(c + 2);
        CP_COMMIT();
    }

#pragma unroll
    for (int mi = 0; mi < 2; mi++)
#pragma unroll
        for (int ni = 0; ni < NI; ni++) {
            const int row = mb + mi * 16 + g;
            const int col = nb + ni * 8 + 2 * qd;
            if (DHALF) {
                __half* D = (__half*)Dv;
                *(__half2*)&D[(size_t)row * ldd + col] =
                    __floats2half2_rn(acc[mi][ni][0], acc[mi][ni][1]);
                *(__half2*)&D[(size_t)(row + 8) * ldd + col] =
                    __floats2half2_rn(acc[mi][ni][2], acc[mi][ni][3]);
            } else {
                float* D = (float*)Dv;
                *(float2*)&D[(size_t)row * ldd + col] =
                    make_float2(acc[mi][ni][0], acc[mi][ni][1]);
                *(float2*)&D[(size_t)(row + 8) * ldd + col] =
                    make_float2(acc[mi][ni][2], acc[mi][ni][3]);
            }
        }
}

// =============================================================================
// Conversion kernels
// =============================================================================
// qT[b][t][c] = fp16(q[b][c][t]);  kT likewise.  grid (16, 128, 16)
__global__ void __launch_bounds__(256) k_cvtqk(const float* __restrict__ q,
                                               const float* __restrict__ kk_)
{
    __shared__ float tile[32][33];
    const int z = blockIdx.z;
    const int b = z >> 1;
    const float* src = (z & 1) ? kk_ : q;
    __half* dst = (z & 1) ? g_kT : g_qT;
    const int t0 = blockIdx.x * 32;
    const int c0 = blockIdx.y * 32;
    const int x = threadIdx.x & 31, y = threadIdx.x >> 5;
#pragma unroll
    for (int j = 0; j < 4; j++)
        tile[y + 8 * j][x] =
            src[(size_t)b * CDIM * TDIM + (size_t)(c0 + y + 8 * j) * TDIM + t0 + x];
    __syncthreads();
#pragma unroll
    for (int j = 0; j < 4; j++)
        dst[(size_t)b * TDIM * CDIM + (size_t)(t0 + y + 8 * j) * CDIM + c0 + x] =
            __float2half_rn(tile[x][y + 8 * j]);
}

// v fp16 in-layout.  grid 16384
__global__ void __launch_bounds__(256) k_cvtv(const float* __restrict__ v)
{
    size_t i = ((size_t)blockIdx.x * 256 + threadIdx.x) * 4;
    float4 a = *(const float4*)&v[i];
    *(__half2*)&g_vh[i]     = __floats2half2_rn(a.x, a.y);
    *(__half2*)&g_vh[i + 2] = __floats2half2_rn(a.z, a.w);
}

// Wk, Wo fp16 in-layout.  grid 512
__global__ void __launch_bounds__(256) k_cvtw(const float* __restrict__ Wk,
                                              const float* __restrict__ Wo)
{
    size_t i = ((size_t)blockIdx.x * 256 + threadIdx.x) * 4;
    const float* src; __half* dst; size_t off;
    if (i < (size_t)NH * HDIM * TDIM) { src = Wk; dst = g_Wkh; off = i; }
    else { src = Wo; dst = g_Woh; off = i - (size_t)NH * HDIM * TDIM; }
    float4 a = *(const float4*)&src[off];
    *(__half2*)&dst[off]     = __floats2half2_rn(a.x, a.y);
    *(__half2*)&dst[off + 2] = __floats2half2_rn(a.z, a.w);
}

// WvT[t][j] = fp16(Wv[j][t]).  grid (16, 16)
__global__ void __launch_bounds__(256) k_cvtwv(const float* __restrict__ Wv)
{
    __shared__ float tile[32][33];
    const int t0 = blockIdx.x * 32;
    const int j0 = blockIdx.y * 32;
    const int x = threadIdx.x & 31, y = threadIdx.x >> 5;
#pragma unroll
    for (int j = 0; j < 4; j++)
        tile[y + 8 * j][x] = Wv[(size_t)(j0 + y + 8 * j) * TDIM + t0 + x];
    __syncthreads();
#pragma unroll
    for (int j = 0; j < 4; j++)
        g_WvT[(size_t)(t0 + y + 8 * j) * TDIM + j0 + x] =
            __float2half_rn(tile[x][y + 8 * j]);
}

// =============================================================================
// K1: P half: g_Pd[b][t][ph*512+s] = sum_{c in half ph} qT[b][t][c] kT[b][s][c]
// split-K=2 -> grid (4,4,16), 256 thr, occ 2.
// =============================================================================
__global__ void __launch_bounds__(256, 2) k_pmat()
{
    const int z  = blockIdx.z;
    const int b  = z >> 1;
    const int ph = z & 1;
    const int t0 = blockIdx.y * 128;
    const int s0 = blockIdx.x * 128;
    const __half* Ab = g_qT + (size_t)b * TDIM * CDIM + (size_t)t0 * CDIM + ph * (CDIM / 2);
    const __half* Bb = g_kT + (size_t)b * TDIM * CDIM + (size_t)s0 * CDIM + ph * (CDIM / 2);
    __half* D = g_Pd + (size_t)b * TDIM * 1024 + (size_t)t0 * 1024 + ph * 512 + s0;
    gemm_h<128, true>(Ab, CDIM, Bb, CDIM, 0xffffffffu, (CDIM / 2) / 32, D, 1024);
}

// =============================================================================
// K2a: U[b,h][t][e] = sum_{k'=0..1023} g_Pd[b][t][k'] * Wk[h][e][k' mod 512]
// grid (4, 8, 8), occ 3.  D = g_U fp32.
// =============================================================================
__global__ void __launch_bounds__(256, 3) k_umat()
{
    const int b  = blockIdx.z;
    const int h  = blockIdx.y;
    const int t0 = blockIdx.x * 128;
    const __half* Ab = g_Pd + (size_t)b * TDIM * 1024 + (size_t)t0 * 1024;
    const __half* Bb = g_Wkh + (size_t)h * HDIM * TDIM;
    float* D = g_U + (size_t)(b * NH + h) * TDIM * HDIM + (size_t)t0 * HDIM;
    gemm_h<64, false>(Ab, 1024, Bb, TDIM, 511u, 1024 / 32, D, HDIM);
}

// =============================================================================
// K2b: per (b,h): S = Wq_h @ U / sqrt(512); W = softmax_rows(S);
// store W^T fp16 -> g_W[bh][e][d]
// =============================================================================
__global__ void __launch_bounds__(256) k_attn(const float* __restrict__ Wq)
{
    const int bh = blockIdx.x;
    const int h = bh & 7;

    __shared__ float Ws[64][65];
    __shared__ float Us[32][68];
    __shared__ float Wqs[64][33];

    const float* Ub  = g_U + (size_t)bh * TDIM * HDIM;
    const float* Wqh = Wq + (size_t)h * HDIM * TDIM;

    const int tid = threadIdx.x;
    const int tx = tid & 15, ty = tid >> 4;

    float acc[4][4];
#pragma unroll
    for (int m = 0; m < 4; m++)
#pragma unroll
        for (int n = 0; n < 4; n++) acc[m][n] = 0.f;

    for (int t0 = 0; t0 < TDIM; t0 += 32) {
#pragma unroll
        for (int i = 0; i < 2; i++) {
            int idx = tid + i * 256;
            int tl  = idx >> 4;
            int eq  = (idx & 15) * 4;
            *(float4*)&Us[tl][eq] = *(const float4*)&Ub[(size_t)(t0 + tl) * HDIM + eq];
        }
#pragma unroll
        for (int i = 0; i < 2; i++) {
            int idx = tid + i * 256;
            int d   = idx >> 3;
            int tq  = (idx & 7) * 4;
            float4 a = *(const float4*)&Wqh[(size_t)d * TDIM + t0 + tq];
            Wqs[d][tq + 0] = a.x; Wqs[d][tq + 1] = a.y;
            Wqs[d][tq + 2] = a.z; Wqs[d][tq + 3] = a.w;
        }
        __syncthreads();
#pragma unroll
        for (int tl = 0; tl < 32; tl++) {
            float ra[4], rb[4];
#pragma unroll
            for (int m = 0; m < 4; m++) ra[m] = Wqs[ty * 4 + m][tl];
#pragma unroll
            for (int n = 0; n < 4; n++) rb[n] = Us[tl][tx * 4 + n];
#pragma unroll
            for (int m = 0; m < 4; m++)
#pragma unroll
                for (int n = 0; n < 4; n++) acc[m][n] += ra[m] * rb[n];
        }
        __syncthreads();
    }

#pragma unroll
    for (int m = 0; m < 4; m++)
#pragma unroll
        for (int n = 0; n < 4; n++)
            Ws[ty * 4 + m][tx * 4 + n] = acc[m][n] * SCALE_INV;
    __syncthreads();

    if (tid < 64) {
        float mx = -1e30f;
#pragma unroll 8
        for (int e = 0; e < 64; e++) mx = fmaxf(mx, Ws[tid][e]);
        float sum = 0.f;
#pragma unroll 8
        for (int e = 0; e < 64; e++) { float ex = expf(Ws[tid][e] - mx); Ws[tid][e] = ex; sum += ex; }
        float inv = 1.f / sum;
#pragma unroll 8
        for (int e = 0; e < 64; e++) Ws[tid][e] *= inv;
    }
    __syncthreads();

    __half* Wt = g_W + (size_t)bh * HDIM * HDIM;
    for (int idx = tid; idx < HDIM * HDIM; idx += 256) {
        int e = idx >> 6, d = idx & 63;
        Wt[(size_t)e * HDIM + d] = __float2half_rn(Ws[d][e]);
    }
}

// =============================================================================
// K2c: Z[b][o][h*64+e] = sum_d Wo[o][h*64+d] * W_h[d][e]
// grid (4 o-tiles, 64 bh), occ 3.
// =============================================================================
__global__ void __launch_bounds__(256, 3) k_zmat()
{
    const int bh = blockIdx.y;
    const int b = bh >> 3, h = bh & 7;
    const int o0 = blockIdx.x * 128;
    const __half* Ab = g_Woh + (size_t)o0 * (NH * HDIM) + h * HDIM;
    const __half* Bb = g_W + (size_t)bh * HDIM * HDIM;
    __half* D = g_Z + (size_t)b * TDIM * TDIM + (size_t)o0 * TDIM + h * HDIM;
    gemm_h<64, true>(Ab, NH * HDIM, Bb, HDIM, 0xffffffffu, HDIM / 32, D, TDIM);
}

// =============================================================================
// K3: G[b][o][t] = sum_j Z[b][o][j] * WvT[t][j]   grid (8, 4, 8), occ 3.
// =============================================================================
__global__ void __launch_bounds__(256, 3) k_gmat()
{
    const int b  = blockIdx.z;
    const int o0 = blockIdx.y * 128;
    const int t0 = blockIdx.x * 64;
    const __half* Ab = g_Z + (size_t)b * TDIM * TDIM + (size_t)o0 * TDIM;
    const __half* Bb = g_WvT + (size_t)t0 * TDIM;
    __half* D = g_G + (size_t)b * TDIM * TDIM + (size_t)o0 * TDIM + t0;
    gemm_h<64, true>(Ab, TDIM, Bb, TDIM, 0xffffffffu, TDIM / 32, D, TDIM);
}

// =============================================================================
// K4: out[b][c][o] = sum_t vh[b][c][t] * G[b][o][t]   grid (4, 32, 8), occ 2.
// =============================================================================
__global__ void __launch_bounds__(256, 2) k_out(float* __restrict__ out)
{
    const int b  = blockIdx.z;
    const int c0 = blockIdx.y * 128;
    const int o0 = blockIdx.x * 128;
    const __half* Ab = g_vh + (size_t)b * CDIM * TDIM + (size_t)c0 * TDIM;
    const __half* Bb = g_G + (size_t)b * TDIM * TDIM + (size_t)o0 * TDIM;
    float* D = out + (size_t)b * CDIM * ODIM + (size_t)c0 * ODIM + o0;
    gemm_h<128, false>(Ab, TDIM, Bb, TDIM, 0xffffffffu, TDIM / 32, D, ODIM);
}

// =============================================================================
extern "C" void kernel_launch(void* const* d_in, const int* in_sizes, int n_in,
                              void* d_out, int out_size)
{
    const float* q  = (const float*)d_in[0];
    const float* k  = (const float*)d_in[1];
    const float* v  = (const float*)d_in[2];
    const float* Wq = (const float*)d_in[3];
    const float* Wk = (const float*)d_in[4];
    const float* Wv = (const float*)d_in[5];
    const float* Wo = (const float*)d_in[6];
    float* out = (float*)d_out;
    (void)in_sizes; (void)n_in; (void)out_size;

    // smem: 3 stages * (128 + NCOLS) * 32 halves * 2B
    const int SM_128 = 3 * (128 + 128) * 32 * 2;   // 49152
    const int SM_64  = 3 * (128 + 64) * 32 * 2;    // 36864

    cudaFuncSetAttribute(k_pmat, cudaFuncAttributeMaxDynamicSharedMemorySize, SM_128);
    cudaFuncSetAttribute(k_umat, cudaFuncAttributeMaxDynamicSharedMemorySize, SM_64);
    cudaFuncSetAttribute(k_zmat, cudaFuncAttributeMaxDynamicSharedMemorySize, SM_64);
    cudaFuncSetAttribute(k_gmat, cudaFuncAttributeMaxDynamicSharedMemorySize, SM_64);
    cudaFuncSetAttribute(k_out,  cudaFuncAttributeMaxDynamicSharedMemorySize, SM_128);

    // conversions
    k_cvtqk<<<dim3(16, 128, 16), 256>>>(q, k);
    k_cvtv <<<16384, 256>>>(v);
    k_cvtw <<<512, 256>>>(Wk, Wo);
    k_cvtwv<<<dim3(16, 16), 256>>>(Wv);

    // pipeline
    k_pmat<<<dim3(4, 4, BSZ * 2), 256, SM_128>>>();
    k_umat<<<dim3(4, NH, BSZ),    256, SM_64>>>();
    k_attn<<<BSZ * NH,            256>>>(Wq);
    k_zmat<<<dim3(4, BSZ * NH),   256, SM_64>>>();
    k_gmat<<<dim3(8, 4, BSZ),     256, SM_64>>>();
    k_out <<<dim3(4, 32, BSZ),    256, SM_128>>>(out);
}

// round 12
// speedup vs baseline: 1.3264x; 1.0323x over previous
#include <cuda_runtime.h>
#include <cuda_fp16.h>
#include <cstdint>
#include <math.h>

// Problem constants
#define BSZ  8
#define CDIM 4096
#define TDIM 512
#define NH   8
#define HDIM 64
#define ODIM 512
#define SCALE_INV (1.0f / 22.62741699796952f)   // 1/sqrt(512)

// ---------------- scratch (static device globals; allocation-free) ----------
__device__ __align__(256) __half g_qT [BSZ * TDIM * CDIM];   // qT[b][t][c]
__device__ __align__(256) __half g_kT [BSZ * TDIM * CDIM];   // kT[b][s][c]
__device__ __align__(256) __half g_vh [BSZ * CDIM * TDIM];   // v fp16 in-layout
__device__ __align__(256) __half g_Wkh[NH * HDIM * TDIM];    // Wk fp16
__device__ __align__(256) __half g_Woh[ODIM * NH * HDIM];    // Wo fp16
__device__ __align__(256) __half g_WvT[TDIM * TDIM];         // WvT[t][j]
// g_Pd[b][t][1024]: cols 0-511 = K-half-0 partial of P, 512-1023 = half-1.
__device__ __align__(256) __half g_Pd [BSZ * TDIM * 1024];
__device__ __align__(256) float  g_U  [BSZ * NH * TDIM * HDIM];
__device__ __align__(256) __half g_W  [BSZ * NH * HDIM * HDIM]; // W^T[e][d]
__device__ __align__(256) __half g_Z  [BSZ * TDIM * TDIM];
__device__ __align__(256) __half g_G  [BSZ * TDIM * TDIM];

// ---------------- helpers ----------------
__device__ __forceinline__ uint32_t smem_u32(const void* p) {
    uint32_t a;
    asm("{ .reg .u64 t; cvta.to.shared.u64 t, %1; cvt.u32.u64 %0, t; }" : "=r"(a) : "l"(p));
    return a;
}

__device__ __forceinline__ void cp16(uint32_t dst, const void* src) {
    asm volatile("cp.async.cg.shared.global [%0], [%1], 16;" :: "r"(dst), "l"(src));
}
#define CP_COMMIT() asm volatile("cp.async.commit_group;" ::: "memory")
#define CP_WAIT1()  asm volatile("cp.async.wait_group 1;"  ::: "memory")

__device__ __forceinline__ void mma_f16(float* c, const unsigned* a, const unsigned* b) {
    asm("mma.sync.aligned.m16n8k16.row.col.f32.f16.f16.f32 "
        "{%0,%1,%2,%3},{%4,%5,%6,%7},{%8,%9},{%0,%1,%2,%3};"
        : "+f"(c[0]), "+f"(c[1]), "+f"(c[2]), "+f"(c[3])
        : "r"(a[0]), "r"(a[1]), "r"(a[2]), "r"(a[3]),
          "r"(b[0]), "r"(b[1]));
}

// XOR-swizzled smem layout: rows of 32 halves, 8-half chunks permuted by
// chunk ^ ((row>>1)&3).  Conflict-free for cp.async 16B stores and LDS.32.
__device__ __forceinline__ int hoff(int row, int chunk) {
    return row * 32 + ((chunk ^ ((row >> 1) & 3)) << 3);
}

// =============================================================================
// Unified fp16 GEMM engine: 128(M) x NCOLS(N) CTA tile, BK=32 (2 k16-steps),
// 256 thr, 3-stage cp.async, all operands K-contiguous fp16 in gmem.
// =============================================================================
template<int NCOLS, bool DHALF>
__device__ __forceinline__ void gemm_h(const __half* __restrict__ A, int lda,
                                       const __half* __restrict__ B, int ldb,
                                       unsigned kmaskB, int NC,
                                       void* __restrict__ Dv, int ldd)
{
    extern __shared__ __half smh[];
    constexpr int ASTAGE = 128 * 32;          // halves
    constexpr int BSTAGE = NCOLS * 32;
    constexpr int STAGE  = ASTAGE + BSTAGE;
    constexpr int NI     = (NCOLS == 128) ? 8 : 4;

    const int tid  = threadIdx.x;
    const int lane = tid & 31;
    const int w    = tid >> 5;
    const int g    = lane >> 2;
    const int qd   = lane & 3;
    const int mb   = (NCOLS == 128) ? (w >> 1) * 32 : (w & 3) * 32;
    const int nb   = (NCOLS == 128) ? (w & 1) * 64 : (w >> 2) * 32;

    auto issue = [&](int c) {
        __half* stA = smh + (c % 3) * STAGE;
#pragma unroll
        for (int it = 0; it < 2; it++) {
            int i = tid + it * 256;
            int row = i >> 2, kc = i & 3;
            cp16(smem_u32(stA + hoff(row, kc)),
                 A + (size_t)row * lda + (size_t)c * 32 + kc * 8);
        }
        __half* stB = stA + ASTAGE;
        unsigned koff = ((unsigned)c * 32u) & kmaskB;
#pragma unroll
        for (int it = 0; it < NCOLS / 64; it++) {
            int i = tid + it * 256;
            int row = i >> 2, kc = i & 3;
            cp16(smem_u32(stB + hoff(row, kc)),
                 B + (size_t)row * ldb + koff + kc * 8);
        }
    };

    float acc[2][NI][4];
#pragma unroll
    for (int mi = 0; mi < 2; mi++)
#pragma unroll
        for (int ni = 0; ni < NI; ni++)
#pragma unroll
            for (int r = 0; r < 4; r++) acc[mi][ni][r] = 0.f;

    issue(0); CP_COMMIT();
    issue(1); CP_COMMIT();

    for (int c = 0; c < NC; c++) {
        CP_WAIT1();
        __syncthreads();
        const unsigned* As = (const unsigned*)(smh + (c % 3) * STAGE);
        const unsigned* Bs = As + ASTAGE / 2;

#pragma unroll
        for (int ks = 0; ks < 2; ks++) {
            unsigned af[2][4], bf[NI][2];
#pragma unroll
            for (int mi = 0; mi < 2; mi++) {
                const int m = mb + mi * 16 + g;
                af[mi][0] = As[hoff(m,     ks * 2)     / 2 + qd];
                af[mi][1] = As[hoff(m + 8, ks * 2)     / 2 + qd];
                af[mi][2] = As[hoff(m,     ks * 2 + 1) / 2 + qd];
                af[mi][3] = As[hoff(m + 8, ks * 2 + 1) / 2 + qd];
            }
#pragma unroll
            for (int ni = 0; ni < NI; ni++) {
                const int n = nb + ni * 8 + g;
                bf[ni][0] = Bs[hoff(n, ks * 2)     / 2 + qd];
                bf[ni][1] = Bs[hoff(n, ks * 2 + 1) / 2 + qd];
            }
#pragma unroll
            for (int mi = 0; mi < 2; mi++)
#pragma unroll
                for (int ni = 0; ni < NI; ni++)
                    mma_f16(acc[mi][ni], af[mi], bf[ni]);
        }

        if (c + 2 < NC) issue(c + 2);
        CP_COMMIT();
    }

#pragma unroll
    for (int mi = 0; mi < 2; mi++)
#pragma unroll
        for (int ni = 0; ni < NI; ni++) {
            const int row = mb + mi * 16 + g;
            const int col = nb + ni * 8 + 2 * qd;
            if (DHALF) {
                __half* D = (__half*)Dv;
                *(__half2*)&D[(size_t)row * ldd + col] =
                    __floats2half2_rn(acc[mi][ni][0], acc[mi][ni][1]);
                *(__half2*)&D[(size_t)(row + 8) * ldd + col] =
                    __floats2half2_rn(acc[mi][ni][2], acc[mi][ni][3]);
            } else {
                float* D = (float*)Dv;
                *(float2*)&D[(size_t)row * ldd + col] =
                    make_float2(acc[mi][ni][0], acc[mi][ni][1]);
                *(float2*)&D[(size_t)(row + 8) * ldd + col] =
                    make_float2(acc[mi][ni][2], acc[mi][ni][3]);
            }
        }
}

// =============================================================================
// Conversion kernels
// =============================================================================
// qT[b][t][c] = fp16(q[b][c][t]) — vectorized: 64c x 32t fp32 tile, uint4
// half stores (128B/warp write transactions).  grid (16, 64, 16)
__global__ void __launch_bounds__(256) k_cvtqk(const float* __restrict__ q,
                                               const float* __restrict__ kk_)
{
    __shared__ float tile[64][33];
    const int z = blockIdx.z;
    const int b = z >> 1;
    const float* src = (z & 1) ? kk_ : q;
    __half* dst = (z & 1) ? g_kT : g_qT;
    const int t0 = blockIdx.x * 32;
    const int c0 = blockIdx.y * 64;
    const int tid = threadIdx.x;

    // phase 1: coalesced fp32 loads, conflict-free STS (bank = c*33+x mod 32)
    {
        const int x = tid & 31;        // t
        const int y = tid >> 5;        // c sub
#pragma unroll
        for (int j = 0; j < 8; j++) {
            int c = y + 8 * j;
            tile[c][x] = src[(size_t)b * CDIM * TDIM + (size_t)(c0 + c) * TDIM + t0 + x];
        }
    }
    __syncthreads();

    // phase 2: gather 8 c-values per thread, convert, uint4 store
    {
        const int t  = tid >> 3;           // 0..31
        const int c8 = (tid & 7) * 8;      // 0..56
        float f[8];
#pragma unroll
        for (int j = 0; j < 8; j++) f[j] = tile[c8 + j][t];
        __half2 h[4];
#pragma unroll
        for (int j = 0; j < 4; j++) h[j] = __floats2half2_rn(f[2 * j], f[2 * j + 1]);
        *(uint4*)&dst[(size_t)b * TDIM * CDIM + (size_t)(t0 + t) * CDIM + c0 + c8] =
            *(uint4*)h;
    }
}

// v, Wk, Wo fp16 in-layout (merged).  grid 16896
__global__ void __launch_bounds__(256) k_cvtlin(const float* __restrict__ v,
                                                const float* __restrict__ Wk,
                                                const float* __restrict__ Wo)
{
    const size_t NV = (size_t)BSZ * CDIM * TDIM;
    const size_t NK = (size_t)NH * HDIM * TDIM;
    size_t i = ((size_t)blockIdx.x * 256 + threadIdx.x) * 4;
    const float* src; __half* dst; size_t off;
    if (i < NV)           { src = v;  dst = g_vh;  off = i; }
    else if (i < NV + NK) { src = Wk; dst = g_Wkh; off = i - NV; }
    else                  { src = Wo; dst = g_Woh; off = i - NV - NK; }
    float4 a = *(const float4*)&src[off];
    *(__half2*)&dst[off]     = __floats2half2_rn(a.x, a.y);
    *(__half2*)&dst[off + 2] = __floats2half2_rn(a.z, a.w);
}

// WvT[t][j] = fp16(Wv[j][t]).  64j x 32t tile, vectorized store.  grid (16, 8)
__global__ void __launch_bounds__(256) k_cvtwv(const float* __restrict__ Wv)
{
    __shared__ float tile[64][33];
    const int t0 = blockIdx.x * 32;
    const int j0 = blockIdx.y * 64;
    const int tid = threadIdx.x;
    {
        const int x = tid & 31;        // t
        const int y = tid >> 5;
#pragma unroll
        for (int jj = 0; jj < 8; jj++) {
            int j = y + 8 * jj;
            tile[j][x] = Wv[(size_t)(j0 + j) * TDIM + t0 + x];
        }
    }
    __syncthreads();
    {
        const int t  = tid >> 3;
        const int j8 = (tid & 7) * 8;
        float f[8];
#pragma unroll
        for (int jj = 0; jj < 8; jj++) f[jj] = tile[j8 + jj][t];
        __half2 h[4];
#pragma unroll
        for (int jj = 0; jj < 4; jj++) h[jj] = __floats2half2_rn(f[2 * jj], f[2 * jj + 1]);
        *(uint4*)&g_WvT[(size_t)(t0 + t) * TDIM + j0 + j8] = *(uint4*)h;
    }
}

// =============================================================================
// K1: P half: g_Pd[b][t][ph*512+s] = sum_{c in half ph} qT[b][t][c] kT[b][s][c]
// =============================================================================
__global__ void __launch_bounds__(256, 2) k_pmat()
{
    const int z  = blockIdx.z;
    const int b  = z >> 1;
    const int ph = z & 1;
    const int t0 = blockIdx.y * 128;
    const int s0 = blockIdx.x * 128;
    const __half* Ab = g_qT + (size_t)b * TDIM * CDIM + (size_t)t0 * CDIM + ph * (CDIM / 2);
    const __half* Bb = g_kT + (size_t)b * TDIM * CDIM + (size_t)s0 * CDIM + ph * (CDIM / 2);
    __half* D = g_Pd + (size_t)b * TDIM * 1024 + (size_t)t0 * 1024 + ph * 512 + s0;
    gemm_h<128, true>(Ab, CDIM, Bb, CDIM, 0xffffffffu, (CDIM / 2) / 32, D, 1024);
}

// =============================================================================
// K2a: U[b,h][t][e] = sum_{k'=0..1023} g_Pd[b][t][k'] * Wk[h][e][k' mod 512]
// =============================================================================
__global__ void __launch_bounds__(256, 3) k_umat()
{
    const int b  = blockIdx.z;
    const int h  = blockIdx.y;
    const int t0 = blockIdx.x * 128;
    const __half* Ab = g_Pd + (size_t)b * TDIM * 1024 + (size_t)t0 * 1024;
    const __half* Bb = g_Wkh + (size_t)h * HDIM * TDIM;
    float* D = g_U + (size_t)(b * NH + h) * TDIM * HDIM + (size_t)t0 * HDIM;
    gemm_h<64, false>(Ab, 1024, Bb, TDIM, 511u, 1024 / 32, D, HDIM);
}

// =============================================================================
// K2b: per (b,h): S = Wq_h @ U / sqrt(512); W = softmax_rows(S);
// store W^T fp16 -> g_W[bh][e][d]
// =============================================================================
__global__ void __launch_bounds__(256) k_attn(const float* __restrict__ Wq)
{
    const int bh = blockIdx.x;
    const int h = bh & 7;

    __shared__ float Ws[64][65];
    __shared__ float Us[32][68];
    __shared__ float Wqs[64][33];

    const float* Ub  = g_U + (size_t)bh * TDIM * HDIM;
    const float* Wqh = Wq + (size_t)h * HDIM * TDIM;

    const int tid = threadIdx.x;
    const int tx = tid & 15, ty = tid >> 4;

    float acc[4][4];
#pragma unroll
    for (int m = 0; m < 4; m++)
#pragma unroll
        for (int n = 0; n < 4; n++) acc[m][n] = 0.f;

    for (int t0 = 0; t0 < TDIM; t0 += 32) {
#pragma unroll
        for (int i = 0; i < 2; i++) {
            int idx = tid + i * 256;
            int tl  = idx >> 4;
            int eq  = (idx & 15) * 4;
            *(float4*)&Us[tl][eq] = *(const float4*)&Ub[(size_t)(t0 + tl) * HDIM + eq];
        }
#pragma unroll
        for (int i = 0; i < 2; i++) {
            int idx = tid + i * 256;
            int d   = idx >> 3;
            int tq  = (idx & 7) * 4;
            float4 a = *(const float4*)&Wqh[(size_t)d * TDIM + t0 + tq];
            Wqs[d][tq + 0] = a.x; Wqs[d][tq + 1] = a.y;
            Wqs[d][tq + 2] = a.z; Wqs[d][tq + 3] = a.w;
        }
        __syncthreads();
#pragma unroll
        for (int tl = 0; tl < 32; tl++) {
            float ra[4], rb[4];
#pragma unroll
            for (int m = 0; m < 4; m++) ra[m] = Wqs[ty * 4 + m][tl];
#pragma unroll
            for (int n = 0; n < 4; n++) rb[n] = Us[tl][tx * 4 + n];
#pragma unroll
            for (int m = 0; m < 4; m++)
#pragma unroll
                for (int n = 0; n < 4; n++) acc[m][n] += ra[m] * rb[n];
        }
        __syncthreads();
    }

#pragma unroll
    for (int m = 0; m < 4; m++)
#pragma unroll
        for (int n = 0; n < 4; n++)
            Ws[ty * 4 + m][tx * 4 + n] = acc[m][n] * SCALE_INV;
    __syncthreads();

    if (tid < 64) {
        float mx = -1e30f;
#pragma unroll 8
        for (int e = 0; e < 64; e++) mx = fmaxf(mx, Ws[tid][e]);
        float sum = 0.f;
#pragma unroll 8
        for (int e = 0; e < 64; e++) { float ex = expf(Ws[tid][e] - mx); Ws[tid][e] = ex; sum += ex; }
        float inv = 1.f / sum;
#pragma unroll 8
        for (int e = 0; e < 64; e++) Ws[tid][e] *= inv;
    }
    __syncthreads();

    __half* Wt = g_W + (size_t)bh * HDIM * HDIM;
    for (int idx = tid; idx < HDIM * HDIM; idx += 256) {
        int e = idx >> 6, d = idx & 63;
        Wt[(size_t)e * HDIM + d] = __float2half_rn(Ws[d][e]);
    }
}

// =============================================================================
// K2c: Z[b][o][h*64+e] = sum_d Wo[o][h*64+d] * W_h[d][e]
// =============================================================================
__global__ void __launch_bounds__(256, 3) k_zmat()
{
    const int bh = blockIdx.y;
    const int b = bh >> 3, h = bh & 7;
    const int o0 = blockIdx.x * 128;
    const __half* Ab = g_Woh + (size_t)o0 * (NH * HDIM) + h * HDIM;
    const __half* Bb = g_W + (size_t)bh * HDIM * HDIM;
    __half* D = g_Z + (size_t)b * TDIM * TDIM + (size_t)o0 * TDIM + h * HDIM;
    gemm_h<64, true>(Ab, NH * HDIM, Bb, HDIM, 0xffffffffu, HDIM / 32, D, TDIM);
}

// =============================================================================
// K3: G[b][o][t] = sum_j Z[b][o][j] * WvT[t][j]
// =============================================================================
__global__ void __launch_bounds__(256, 3) k_gmat()
{
    const int b  = blockIdx.z;
    const int o0 = blockIdx.y * 128;
    const int t0 = blockIdx.x * 64;
    const __half* Ab = g_Z + (size_t)b * TDIM * TDIM + (size_t)o0 * TDIM;
    const __half* Bb = g_WvT + (size_t)t0 * TDIM;
    __half* D = g_G + (size_t)b * TDIM * TDIM + (size_t)o0 * TDIM + t0;
    gemm_h<64, true>(Ab, TDIM, Bb, TDIM, 0xffffffffu, TDIM / 32, D, TDIM);
}

// =============================================================================
// K4: out[b][c][o] = sum_t vh[b][c][t] * G[b][o][t]
// =============================================================================
__global__ void __launch_bounds__(256, 2) k_out(float* __restrict__ out)
{
    const int b  = blockIdx.z;
    const int c0 = blockIdx.y * 128;
    const int o0 = blockIdx.x * 128;
    const __half* Ab = g_vh + (size_t)b * CDIM * TDIM + (size_t)c0 * TDIM;
    const __half* Bb = g_G + (size_t)b * TDIM * TDIM + (size_t)o0 * TDIM;
    float* D = out + (size_t)b * CDIM * ODIM + (size_t)c0 * ODIM + o0;
    gemm_h<128, false>(Ab, TDIM, Bb, TDIM, 0xffffffffu, TDIM / 32, D, ODIM);
}

// =============================================================================
extern "C" void kernel_launch(void* const* d_in, const int* in_sizes, int n_in,
                              void* d_out, int out_size)
{
    const float* q  = (const float*)d_in[0];
    const float* k  = (const float*)d_in[1];
    const float* v  = (const float*)d_in[2];
    const float* Wq = (const float*)d_in[3];
    const float* Wk = (const float*)d_in[4];
    const float* Wv = (const float*)d_in[5];
    const float* Wo = (const float*)d_in[6];
    float* out = (float*)d_out;
    (void)in_sizes; (void)n_in; (void)out_size;

    const int SM_128 = 3 * (128 + 128) * 32 * 2;   // 49152
    const int SM_64  = 3 * (128 + 64) * 32 * 2;    // 36864

    cudaFuncSetAttribute(k_pmat, cudaFuncAttributeMaxDynamicSharedMemorySize, SM_128);
    cudaFuncSetAttribute(k_umat, cudaFuncAttributeMaxDynamicSharedMemorySize, SM_64);
    cudaFuncSetAttribute(k_zmat, cudaFuncAttributeMaxDynamicSharedMemorySize, SM_64);
    cudaFuncSetAttribute(k_gmat, cudaFuncAttributeMaxDynamicSharedMemorySize, SM_64);
    cudaFuncSetAttribute(k_out,  cudaFuncAttributeMaxDynamicSharedMemorySize, SM_128);

    // conversions
    k_cvtqk<<<dim3(16, 64, 16), 256>>>(q, k);
    k_cvtlin<<<16896, 256>>>(v, Wk, Wo);
    k_cvtwv<<<dim3(16, 8), 256>>>(Wv);

    // pipeline
    k_pmat<<<dim3(4, 4, BSZ * 2), 256, SM_128>>>();
    k_umat<<<dim3(4, NH, BSZ),    256, SM_64>>>();
    k_attn<<<BSZ * NH,            256>>>(Wq);
    k_zmat<<<dim3(4, BSZ * NH),   256, SM_64>>>();
    k_gmat<<<dim3(8, 4, BSZ),     256, SM_64>>>();
    k_out <<<dim3(4, 32, BSZ),    256, SM_128>>>(out);
}

// round 13
// speedup vs baseline: 1.5989x; 1.2055x over previous
#include <cuda_runtime.h>
#include <cuda_fp16.h>
#include <cstdint>
#include <math.h>

// Problem constants
#define BSZ  8
#define CDIM 4096
#define TDIM 512
#define NH   8
#define HDIM 64
#define ODIM 512
#define SCALE_INV (1.0f / 22.62741699796952f)   // 1/sqrt(512)

// ---------------- scratch (static device globals; allocation-free) ----------
__device__ __align__(256) __half g_qT [BSZ * TDIM * CDIM];   // qT[b][t][c]
__device__ __align__(256) __half g_kT [BSZ * TDIM * CDIM];   // kT[b][s][c]
__device__ __align__(256) __half g_vh [BSZ * CDIM * TDIM];   // v fp16 in-layout
__device__ __align__(256) __half g_Wkh[NH * HDIM * TDIM];    // Wk fp16
__device__ __align__(256) __half g_Woh[ODIM * NH * HDIM];    // Wo fp16
__device__ __align__(256) __half g_WvT[TDIM * TDIM];         // WvT[t][j]
// g_Pd[b][t][1024]: cols 0-511 = K-half-0 partial of P, 512-1023 = half-1.
__device__ __align__(256) __half g_Pd [BSZ * TDIM * 1024];
__device__ __align__(256) float  g_U  [BSZ * NH * TDIM * HDIM];
__device__ __align__(256) __half g_W  [BSZ * NH * HDIM * HDIM]; // W^T[e][d]
__device__ __align__(256) __half g_Z  [BSZ * TDIM * TDIM];
__device__ __align__(256) __half g_G  [BSZ * TDIM * TDIM];

// ---------------- helpers ----------------
__device__ __forceinline__ uint32_t smem_u32(const void* p) {
    uint32_t a;
    asm("{ .reg .u64 t; cvta.to.shared.u64 t, %1; cvt.u32.u64 %0, t; }" : "=r"(a) : "l"(p));
    return a;
}

__device__ __forceinline__ void cp16(uint32_t dst, const void* src) {
    asm volatile("cp.async.cg.shared.global [%0], [%1], 16;" :: "r"(dst), "l"(src));
}
#define CP_COMMIT() asm volatile("cp.async.commit_group;" ::: "memory")
#define CP_WAIT1()  asm volatile("cp.async.wait_group 1;"  ::: "memory")

__device__ __forceinline__ void mma_f16(float* c, const unsigned* a, const unsigned* b) {
    asm("mma.sync.aligned.m16n8k16.row.col.f32.f16.f16.f32 "
        "{%0,%1,%2,%3},{%4,%5,%6,%7},{%8,%9},{%0,%1,%2,%3};"
        : "+f"(c[0]), "+f"(c[1]), "+f"(c[2]), "+f"(c[3])
        : "r"(a[0]), "r"(a[1]), "r"(a[2]), "r"(a[3]),
          "r"(b[0]), "r"(b[1]));
}

__device__ __forceinline__ void ldsm4(unsigned* r, uint32_t addr) {
    asm volatile("ldmatrix.sync.aligned.m8n8.x4.shared.b16 {%0,%1,%2,%3}, [%4];"
        : "=r"(r[0]), "=r"(r[1]), "=r"(r[2]), "=r"(r[3]) : "r"(addr));
}

// XOR-swizzled smem layout: rows of 32 halves, 8-half chunks permuted by
// chunk ^ ((row>>1)&3).  Conflict-free for cp.async stores and LDSM rows.
__device__ __forceinline__ int hoff(int row, int chunk) {
    return row * 32 + ((chunk ^ ((row >> 1) & 3)) << 3);
}

// =============================================================================
// Unified fp16 GEMM engine: 128(M) x NCOLS(N) CTA tile, BK=32 (2 k16-steps),
// 256 thr, 3-stage cp.async, ldmatrix fragment loads with hoisted offsets.
// =============================================================================
template<int NCOLS, bool DHALF>
__device__ __forceinline__ void gemm_h(const __half* __restrict__ A, int lda,
                                       const __half* __restrict__ B, int ldb,
                                       unsigned kmaskB, int NC,
                                       void* __restrict__ Dv, int ldd)
{
    extern __shared__ __half smh[];
    constexpr int ASTAGE = 128 * 32;          // halves
    constexpr int BSTAGE = NCOLS * 32;
    constexpr int STAGE  = ASTAGE + BSTAGE;
    constexpr int NI     = (NCOLS == 128) ? 8 : 4;
    constexpr int NP     = NI / 2;

    const int tid  = threadIdx.x;
    const int lane = tid & 31;
    const int w    = tid >> 5;
    const int g    = lane >> 2;
    const int qd   = lane & 3;
    const int mb   = (NCOLS == 128) ? (w >> 1) * 32 : (w & 3) * 32;
    const int nb   = (NCOLS == 128) ? (w & 1) * 64 : (w >> 2) * 32;

    // per-lane ldmatrix byte offsets (loop-invariant)
    // A x4: mat0/1 = rows 0-7/8-15 of chunk ks*2; mat2/3 = same rows of ks*2+1
    int aoff[2][2];
    {
        const int arow = (lane & 7) + ((lane >> 3) & 1) * 8;
        const int achk = lane >> 4;
#pragma unroll
        for (int mi = 0; mi < 2; mi++)
#pragma unroll
            for (int ks = 0; ks < 2; ks++)
                aoff[mi][ks] = hoff(mb + mi * 16 + arow, ks * 2 + achk) * 2;
    }
    // B x4 (two n-tiles): mat0/1 = rows ni, chunks ks*2 / ks*2+1; mat2/3 = ni+1
    int boff[NP][2];
    {
        const int brow = ((lane >> 4) << 3) + (lane & 7);
        const int bchk = (lane >> 3) & 1;
#pragma unroll
        for (int np = 0; np < NP; np++)
#pragma unroll
            for (int ks = 0; ks < 2; ks++)
                boff[np][ks] = hoff(nb + np * 16 + brow, ks * 2 + bchk) * 2;
    }

    auto issue = [&](int c) {
        __half* stA = smh + (c % 3) * STAGE;
#pragma unroll
        for (int it = 0; it < 2; it++) {
            int i = tid + it * 256;
            int row = i >> 2, kc = i & 3;
            cp16(smem_u32(stA + hoff(row, kc)),
                 A + (size_t)row * lda + (size_t)c * 32 + kc * 8);
        }
        __half* stB = stA + ASTAGE;
        unsigned koff = ((unsigned)c * 32u) & kmaskB;
#pragma unroll
        for (int it = 0; it < NCOLS / 64; it++) {
            int i = tid + it * 256;
            int row = i >> 2, kc = i & 3;
            cp16(smem_u32(stB + hoff(row, kc)),
                 B + (size_t)row * ldb + koff + kc * 8);
        }
    };

    float acc[2][NI][4];
#pragma unroll
    for (int mi = 0; mi < 2; mi++)
#pragma unroll
        for (int ni = 0; ni < NI; ni++)
#pragma unroll
            for (int r = 0; r < 4; r++) acc[mi][ni][r] = 0.f;

    issue(0); CP_COMMIT();
    issue(1); CP_COMMIT();

    const uint32_t smbase = smem_u32(smh);

    for (int c = 0; c < NC; c++) {
        CP_WAIT1();
        __syncthreads();
        const uint32_t abase = smbase + (c % 3) * (STAGE * 2);
        const uint32_t bbase = abase + ASTAGE * 2;

#pragma unroll
        for (int ks = 0; ks < 2; ks++) {
            unsigned af[2][4];
            ldsm4(af[0], abase + aoff[0][ks]);
            ldsm4(af[1], abase + aoff[1][ks]);
            unsigned bf[NI][2];
#pragma unroll
            for (int np = 0; np < NP; np++)
                ldsm4(&bf[2 * np][0], bbase + boff[np][ks]);
#pragma unroll
            for (int mi = 0; mi < 2; mi++)
#pragma unroll
                for (int ni = 0; ni < NI; ni++)
                    mma_f16(acc[mi][ni], af[mi], bf[ni]);
        }

        if (c + 2 < NC) issue(c + 2);
        CP_COMMIT();
    }

#pragma unroll
    for (int mi = 0; mi < 2; mi++)
#pragma unroll
        for (int ni = 0; ni < NI; ni++) {
            const int row = mb + mi * 16 + g;
            const int col = nb + ni * 8 + 2 * qd;
            if (DHALF) {
                __half* D = (__half*)Dv;
                *(__half2*)&D[(size_t)row * ldd + col] =
                    __floats2half2_rn(acc[mi][ni][0], acc[mi][ni][1]);
                *(__half2*)&D[(size_t)(row + 8) * ldd + col] =
                    __floats2half2_rn(acc[mi][ni][2], acc[mi][ni][3]);
            } else {
                float* D = (float*)Dv;
                *(float2*)&D[(size_t)row * ldd + col] =
                    make_float2(acc[mi][ni][0], acc[mi][ni][1]);
                *(float2*)&D[(size_t)(row + 8) * ldd + col] =
                    make_float2(acc[mi][ni][2], acc[mi][ni][3]);
            }
        }
}

// =============================================================================
// Conversion kernels (unchanged from R12)
// =============================================================================
__global__ void __launch_bounds__(256) k_cvtqk(const float* __restrict__ q,
                                               const float* __restrict__ kk_)
{
    __shared__ float tile[64][33];
    const int z = blockIdx.z;
    const int b = z >> 1;
    const float* src = (z & 1) ? kk_ : q;
    __half* dst = (z & 1) ? g_kT : g_qT;
    const int t0 = blockIdx.x * 32;
    const int c0 = blockIdx.y * 64;
    const int tid = threadIdx.x;
    {
        const int x = tid & 31;
        const int y = tid >> 5;
#pragma unroll
        for (int j = 0; j < 8; j++) {
            int c = y + 8 * j;
            tile[c][x] = src[(size_t)b * CDIM * TDIM + (size_t)(c0 + c) * TDIM + t0 + x];
        }
    }
    __syncthreads();
    {
        const int t  = tid >> 3;
        const int c8 = (tid & 7) * 8;
        float f[8];
#pragma unroll
        for (int j = 0; j < 8; j++) f[j] = tile[c8 + j][t];
        __half2 h[4];
#pragma unroll
        for (int j = 0; j < 4; j++) h[j] = __floats2half2_rn(f[2 * j], f[2 * j + 1]);
        *(uint4*)&dst[(size_t)b * TDIM * CDIM + (size_t)(t0 + t) * CDIM + c0 + c8] =
            *(uint4*)h;
    }
}

__global__ void __launch_bounds__(256) k_cvtlin(const float* __restrict__ v,
                                                const float* __restrict__ Wk,
                                                const float* __restrict__ Wo)
{
    const size_t NV = (size_t)BSZ * CDIM * TDIM;
    const size_t NK = (size_t)NH * HDIM * TDIM;
    size_t i = ((size_t)blockIdx.x * 256 + threadIdx.x) * 4;
    const float* src; __half* dst; size_t off;
    if (i < NV)           { src = v;  dst = g_vh;  off = i; }
    else if (i < NV + NK) { src = Wk; dst = g_Wkh; off = i - NV; }
    else                  { src = Wo; dst = g_Woh; off = i - NV - NK; }
    float4 a = *(const float4*)&src[off];
    *(__half2*)&dst[off]     = __floats2half2_rn(a.x, a.y);
    *(__half2*)&dst[off + 2] = __floats2half2_rn(a.z, a.w);
}

__global__ void __launch_bounds__(256) k_cvtwv(const float* __restrict__ Wv)
{
    __shared__ float tile[64][33];
    const int t0 = blockIdx.x * 32;
    const int j0 = blockIdx.y * 64;
    const int tid = threadIdx.x;
    {
        const int x = tid & 31;
        const int y = tid >> 5;
#pragma unroll
        for (int jj = 0; jj < 8; jj++) {
            int j = y + 8 * jj;
            tile[j][x] = Wv[(size_t)(j0 + j) * TDIM + t0 + x];
        }
    }
    __syncthreads();
    {
        const int t  = tid >> 3;
        const int j8 = (tid & 7) * 8;
        float f[8];
#pragma unroll
        for (int jj = 0; jj < 8; jj++) f[jj] = tile[j8 + jj][t];
        __half2 h[4];
#pragma unroll
        for (int jj = 0; jj < 4; jj++) h[jj] = __floats2half2_rn(f[2 * jj], f[2 * jj + 1]);
        *(uint4*)&g_WvT[(size_t)(t0 + t) * TDIM + j0 + j8] = *(uint4*)h;
    }
}

// =============================================================================
// K1: P half: g_Pd[b][t][ph*512+s] = sum_{c in half ph} qT[b][t][c] kT[b][s][c]
// =============================================================================
__global__ void __launch_bounds__(256, 2) k_pmat()
{
    const int z  = blockIdx.z;
    const int b  = z >> 1;
    const int ph = z & 1;
    const int t0 = blockIdx.y * 128;
    const int s0 = blockIdx.x * 128;
    const __half* Ab = g_qT + (size_t)b * TDIM * CDIM + (size_t)t0 * CDIM + ph * (CDIM / 2);
    const __half* Bb = g_kT + (size_t)b * TDIM * CDIM + (size_t)s0 * CDIM + ph * (CDIM / 2);
    __half* D = g_Pd + (size_t)b * TDIM * 1024 + (size_t)t0 * 1024 + ph * 512 + s0;
    gemm_h<128, true>(Ab, CDIM, Bb, CDIM, 0xffffffffu, (CDIM / 2) / 32, D, 1024);
}

// =============================================================================
// K2a: U[b,h][t][e] = sum_{k'=0..1023} g_Pd[b][t][k'] * Wk[h][e][k' mod 512]
// =============================================================================
__global__ void __launch_bounds__(256, 3) k_umat()
{
    const int b  = blockIdx.z;
    const int h  = blockIdx.y;
    const int t0 = blockIdx.x * 128;
    const __half* Ab = g_Pd + (size_t)b * TDIM * 1024 + (size_t)t0 * 1024;
    const __half* Bb = g_Wkh + (size_t)h * HDIM * TDIM;
    float* D = g_U + (size_t)(b * NH + h) * TDIM * HDIM + (size_t)t0 * HDIM;
    gemm_h<64, false>(Ab, 1024, Bb, TDIM, 511u, 1024 / 32, D, HDIM);
}

// =============================================================================
// K2b: per (b,h): S = Wq_h @ U / sqrt(512); W = softmax_rows(S);
// store W^T fp16 -> g_W[bh][e][d]
// =============================================================================
__global__ void __launch_bounds__(256) k_attn(const float* __restrict__ Wq)
{
    const int bh = blockIdx.x;
    const int h = bh & 7;

    __shared__ float Ws[64][65];
    __shared__ float Us[32][68];
    __shared__ float Wqs[64][33];

    const float* Ub  = g_U + (size_t)bh * TDIM * HDIM;
    const float* Wqh = Wq + (size_t)h * HDIM * TDIM;

    const int tid = threadIdx.x;
    const int tx = tid & 15, ty = tid >> 4;

    float acc[4][4];
#pragma unroll
    for (int m = 0; m < 4; m++)
#pragma unroll
        for (int n = 0; n < 4; n++) acc[m][n] = 0.f;

    for (int t0 = 0; t0 < TDIM; t0 += 32) {
#pragma unroll
        for (int i = 0; i < 2; i++) {
            int idx = tid + i * 256;
            int tl  = idx >> 4;
            int eq  = (idx & 15) * 4;
            *(float4*)&Us[tl][eq] = *(const float4*)&Ub[(size_t)(t0 + tl) * HDIM + eq];
        }
#pragma unroll
        for (int i = 0; i < 2; i++) {
            int idx = tid + i * 256;
            int d   = idx >> 3;
            int tq  = (idx & 7) * 4;
            float4 a = *(const float4*)&Wqh[(size_t)d * TDIM + t0 + tq];
            Wqs[d][tq + 0] = a.x; Wqs[d][tq + 1] = a.y;
            Wqs[d][tq + 2] = a.z; Wqs[d][tq + 3] = a.w;
        }
        __syncthreads();
#pragma unroll
        for (int tl = 0; tl < 32; tl++) {
            float ra[4], rb[4];
#pragma unroll
            for (int m = 0; m < 4; m++) ra[m] = Wqs[ty * 4 + m][tl];
#pragma unroll
            for (int n = 0; n < 4; n++) rb[n] = Us[tl][tx * 4 + n];
#pragma unroll
            for (int m = 0; m < 4; m++)
#pragma unroll
                for (int n = 0; n < 4; n++) acc[m][n] += ra[m] * rb[n];
        }
        __syncthreads();
    }

#pragma unroll
    for (int m = 0; m < 4; m++)
#pragma unroll
        for (int n = 0; n < 4; n++)
            Ws[ty * 4 + m][tx * 4 + n] = acc[m][n] * SCALE_INV;
    __syncthreads();

    if (tid < 64) {
        float mx = -1e30f;
#pragma unroll 8
        for (int e = 0; e < 64; e++) mx = fmaxf(mx, Ws[tid][e]);
        float sum = 0.f;
#pragma unroll 8
        for (int e = 0; e < 64; e++) { float ex = expf(Ws[tid][e] - mx); Ws[tid][e] = ex; sum += ex; }
        float inv = 1.f / sum;
#pragma unroll 8
        for (int e = 0; e < 64; e++) Ws[tid][e] *= inv;
    }
    __syncthreads();

    __half* Wt = g_W + (size_t)bh * HDIM * HDIM;
    for (int idx = tid; idx < HDIM * HDIM; idx += 256) {
        int e = idx >> 6, d = idx & 63;
        Wt[(size_t)e * HDIM + d] = __float2half_rn(Ws[d][e]);
    }
}

// =============================================================================
// K2c: Z[b][o][h*64+e] = sum_d Wo[o][h*64+d] * W_h[d][e]
// =============================================================================
__global__ void __launch_bounds__(256, 3) k_zmat()
{
    const int bh = blockIdx.y;
    const int b = bh >> 3, h = bh & 7;
    const int o0 = blockIdx.x * 128;
    const __half* Ab = g_Woh + (size_t)o0 * (NH * HDIM) + h * HDIM;
    const __half* Bb = g_W + (size_t)bh * HDIM * HDIM;
    __half* D = g_Z + (size_t)b * TDIM * TDIM + (size_t)o0 * TDIM + h * HDIM;
    gemm_h<64, true>(Ab, NH * HDIM, Bb, HDIM, 0xffffffffu, HDIM / 32, D, TDIM);
}

// =============================================================================
// K3: G[b][o][t] = sum_j Z[b][o][j] * WvT[t][j]
// =============================================================================
__global__ void __launch_bounds__(256, 3) k_gmat()
{
    const int b  = blockIdx.z;
    const int o0 = blockIdx.y * 128;
    const int t0 = blockIdx.x * 64;
    const __half* Ab = g_Z + (size_t)b * TDIM * TDIM + (size_t)o0 * TDIM;
    const __half* Bb = g_WvT + (size_t)t0 * TDIM;
    __half* D = g_G + (size_t)b * TDIM * TDIM + (size_t)o0 * TDIM + t0;
    gemm_h<64, true>(Ab, TDIM, Bb, TDIM, 0xffffffffu, TDIM / 32, D, TDIM);
}

// =============================================================================
// K4: out[b][c][o] = sum_t vh[b][c][t] * G[b][o][t]
// =============================================================================
__global__ void __launch_bounds__(256, 2) k_out(float* __restrict__ out)
{
    const int b  = blockIdx.z;
    const int c0 = blockIdx.y * 128;
    const int o0 = blockIdx.x * 128;
    const __half* Ab = g_vh + (size_t)b * CDIM * TDIM + (size_t)c0 * TDIM;
    const __half* Bb = g_G + (size_t)b * TDIM * TDIM + (size_t)o0 * TDIM;
    float* D = out + (size_t)b * CDIM * ODIM + (size_t)c0 * ODIM + o0;
    gemm_h<128, false>(Ab, TDIM, Bb, TDIM, 0xffffffffu, TDIM / 32, D, ODIM);
}

// =============================================================================
extern "C" void kernel_launch(void* const* d_in, const int* in_sizes, int n_in,
                              void* d_out, int out_size)
{
    const float* q  = (const float*)d_in[0];
    const float* k  = (const float*)d_in[1];
    const float* v  = (const float*)d_in[2];
    const float* Wq = (const float*)d_in[3];
    const float* Wk = (const float*)d_in[4];
    const float* Wv = (const float*)d_in[5];
    const float* Wo = (const float*)d_in[6];
    float* out = (float*)d_out;
    (void)in_sizes; (void)n_in; (void)out_size;

    const int SM_128 = 3 * (128 + 128) * 32 * 2;   // 49152
    const int SM_64  = 3 * (128 + 64) * 32 * 2;    // 36864

    cudaFuncSetAttribute(k_pmat, cudaFuncAttributeMaxDynamicSharedMemorySize, SM_128);
    cudaFuncSetAttribute(k_umat, cudaFuncAttributeMaxDynamicSharedMemorySize, SM_64);
    cudaFuncSetAttribute(k_zmat, cudaFuncAttributeMaxDynamicSharedMemorySize, SM_64);
    cudaFuncSetAttribute(k_gmat, cudaFuncAttributeMaxDynamicSharedMemorySize, SM_64);
    cudaFuncSetAttribute(k_out,  cudaFuncAttributeMaxDynamicSharedMemorySize, SM_128);

    // conversions
    k_cvtqk<<<dim3(16, 64, 16), 256>>>(q, k);
    k_cvtlin<<<16896, 256>>>(v, Wk, Wo);
    k_cvtwv<<<dim3(16, 8), 256>>>(Wv);

    // pipeline
    k_pmat<<<dim3(4, 4, BSZ * 2), 256, SM_128>>>();
    k_umat<<<dim3(4, NH, BSZ),    256, SM_64>>>();
    k_attn<<<BSZ * NH,            256>>>(Wq);
    k_zmat<<<dim3(4, BSZ * NH),   256, SM_64>>>();
    k_gmat<<<dim3(8, 4, BSZ),     256, SM_64>>>();
    k_out <<<dim3(4, 32, BSZ),    256, SM_128>>>(out);
}